// round 11
// baseline (speedup 1.0000x reference)
#include <cuda_runtime.h>
#include <cuda_fp16.h>
#include <stdint.h>
#include <math.h>

#define BB 2
#define SS 1024
#define DD 256
#define HH 4
#define CC 64
#define WINSZ 10
#define NITER 2
#define MM 2048
#define HID 2048
#define BSD (BB*SS*DD)
#define MH ((size_t)MM*HID)
#define MD ((size_t)MM*DD)

typedef __half hf;

// ---------------- scratch (device globals; no allocation) -------------------
__device__ float g_Q[3*BSD], g_Kb[3*BSD], g_Vb[3*BSD], g_Gb[3*BSD];
__device__ float g_b56[DD];
__device__ float g_part[12*MD];
__device__ hf g_lnh[4*BSD], g_lnl[4*BSD];
__device__ hf g_cth[3*BSD], g_ctl[3*BSD];
__device__ hf g_hidh[3*MH], g_hidl[3*MH];

// fp16 transposed weights [N][K] (single precision level on B side)
__device__ hf g_WqT[7*DD*DD], g_WkT[7*DD*DD], g_WvT[7*DD*DD];
__device__ hf g_GwT[7*DD*DD], g_OwT[7*DD*DD];
__device__ hf g_w1T[(size_t)6*DD*HID];
__device__ hf g_w2T[(size_t)6*HID*DD];

__device__ __forceinline__ void split2h(float v, hf& h, hf& l){
    h = __float2half_rn(v);
    l = __float2half_rn(v - __half2float(h));
}
__device__ __forceinline__ uint32_t smem_u32(const void* p){
    uint32_t a;
    asm("{ .reg .u64 t; cvta.to.shared.u64 t, %1; cvt.u32.u64 %0, t; }" : "=r"(a) : "l"(p));
    return a;
}
__device__ __forceinline__ void cp16(uint32_t saddr, const void* g){
    asm volatile("cp.async.cg.shared.global [%0], [%1], 16;" :: "r"(saddr), "l"(g));
}
__device__ __forceinline__ void ldsm_x4(uint32_t* r, uint32_t addr){
    asm volatile("ldmatrix.sync.aligned.m8n8.x4.shared.b16 {%0,%1,%2,%3}, [%4];"
        : "=r"(r[0]), "=r"(r[1]), "=r"(r[2]), "=r"(r[3]) : "r"(addr));
}

// ---------------- weight transpose to fp16: W[K,N] -> T[N][K] ---------------
__device__ __forceinline__ void wT_body(const float* w, hf* th, int N, int ldt)
{
    __shared__ float sm[32][33];
    int n0 = blockIdx.x * 32, k0 = blockIdx.y * 32;
    int tx = threadIdx.x & 31, ty = threadIdx.x >> 5;
    #pragma unroll
    for (int i = 0; i < 4; i++)
        sm[ty + i*8][tx] = w[(size_t)(k0 + ty + i*8) * N + n0 + tx];
    __syncthreads();
    #pragma unroll
    for (int i = 0; i < 4; i++) {
        int n = n0 + ty + i*8;
        th[(size_t)n * ldt + k0 + tx] = __float2half_rn(sm[tx][ty + i*8]);
    }
}

struct WsAll { const float* src[5]; hf* th[5]; };
__global__ void __launch_bounds__(256) wsplit_all(WsAll wa)
{
    int fam = blockIdx.z / 7, mod = blockIdx.z % 7;
    wT_body(wa.src[fam] + (size_t)mod*DD*DD, wa.th[fam] + (size_t)mod*DD*DD, DD, DD);
}
__global__ void __launch_bounds__(256) wsplit_big(
    const float* __restrict__ W, hf* __restrict__ Th,
    int K, int N, long long wstride, long long tstride)
{
    wT_body(W + (size_t)blockIdx.z * wstride, Th + (size_t)blockIdx.z * tstride, N, K);
}
__global__ void b56_kernel(const float* __restrict__ aOb){
    int t = threadIdx.x;
    g_b56[t] = aOb[5*DD + t] + aOb[6*DD + t];
}

// ---------------- LayerNorm (batched over z), split fp16 output -------------
struct LnS { const float* x; const float* g; const float* b; hf* oh; hf* ol; };
struct LnBatch { LnS s[3]; };

__global__ void __launch_bounds__(256) ln_kernel(LnBatch lb)
{
    LnS sl = lb.s[blockIdx.y];
    int row = blockIdx.x;
    int t   = threadIdx.x;
    float v = sl.x[(size_t)row * DD + t];
    __shared__ float red[8];
    __shared__ float mean_s, rstd_s;
    float s = v;
    #pragma unroll
    for (int o = 16; o > 0; o >>= 1) s += __shfl_xor_sync(0xffffffffu, s, o);
    if ((t & 31) == 0) red[t >> 5] = s;
    __syncthreads();
    if (t == 0) { float tot=0.f; for (int i=0;i<8;i++) tot+=red[i]; mean_s = tot*(1.0f/DD); }
    __syncthreads();
    float d = v - mean_s;
    s = d * d;
    #pragma unroll
    for (int o = 16; o > 0; o >>= 1) s += __shfl_xor_sync(0xffffffffu, s, o);
    if ((t & 31) == 0) red[t >> 5] = s;
    __syncthreads();
    if (t == 0) { float tot=0.f; for (int i=0;i<8;i++) tot+=red[i]; rstd_s = rsqrtf(tot*(1.0f/DD)+1e-5f); }
    __syncthreads();
    float out = d * rstd_s * sl.g[t] + sl.b[t];
    hf h, l; split2h(out, h, l);
    sl.oh[(size_t)row * DD + t] = h;
    sl.ol[(size_t)row * DD + t] = l;
}

// ---------------- split-K reduce: dst = sum(partials) + bias + res ----------
struct RdS { const float* p; const float* bias; const float* res; float* dst; int nsplit; };
struct RdBatch { RdS s[3]; };

__global__ void __launch_bounds__(256) reduce_kernel(RdBatch rb)
{
    RdS sl = rb.s[blockIdx.y];
    size_t idx = ((size_t)blockIdx.x * 256 + threadIdx.x) * 4;
    float4 a = *(const float4*)&sl.p[idx];
    for (int s = 1; s < sl.nsplit; s++) {
        float4 b = *(const float4*)&sl.p[(size_t)s * MD + idx];
        a.x += b.x; a.y += b.y; a.z += b.z; a.w += b.w;
    }
    int col = (int)(idx & (DD - 1));
    float4 bi = *(const float4*)&sl.bias[col];
    a.x += bi.x; a.y += bi.y; a.z += bi.z; a.w += bi.w;
    float4 r4 = *(const float4*)&sl.res[idx];
    a.x += r4.x; a.y += r4.y; a.z += r4.z; a.w += r4.w;
    *(float4*)&sl.dst[idx] = a;
}

// ---------------- batched 2-pass fp16 MMA GEMM ------------------------------
// C[M,N] = epi(A[M,K] @ W[K,N] + bias) (+res); A = Ah + Al (fp16 pair), B fp16
struct Slice {
    const hf *Ah, *Al, *Bh;
    const float *bias, *res;
    float* C; hf *Ch, *Cl;
    int mode, lda, ldb, Ksub;
};
struct Batch { Slice s[12]; };

#define BKC 32
#define LDSB 40
#define ARRE (128*LDSB)
#define STGE (3*ARRE)
#define GSMEM (2*STGE*2)

__device__ __forceinline__ void mma16816h(float* c, const uint32_t* a, const uint32_t* b){
    asm volatile("mma.sync.aligned.m16n8k16.row.col.f32.f16.f16.f32 "
        "{%0,%1,%2,%3}, {%4,%5,%6,%7}, {%8,%9}, {%0,%1,%2,%3};"
        : "+f"(c[0]), "+f"(c[1]), "+f"(c[2]), "+f"(c[3])
        : "r"(a[0]), "r"(a[1]), "r"(a[2]), "r"(a[3]), "r"(b[0]), "r"(b[1]));
}

__global__ void __launch_bounds__(256,2)
gemm_batched(Batch bt, int M, int N)
{
    extern __shared__ __align__(16) hf smem[];
    const Slice sl = bt.s[blockIdx.z];
    const int tid  = threadIdx.x;
    const int warp = tid >> 5, lane = tid & 31;
    const int wm = warp >> 2, wn = warp & 3;
    const int row0 = blockIdx.y * 128, col0 = blockIdx.x * 128;
    const int g8 = lane >> 2, tig = lane & 3;
    const uint32_t sb = smem_u32(smem);
    const int NC = sl.Ksub / BKC;
    const int lda = sl.lda, ldb = sl.ldb;

    float acc[4][4][4];
    #pragma unroll
    for (int i=0;i<4;i++) for (int j=0;j<4;j++) for (int q=0;q<4;q++) acc[i][j][q]=0.f;

    const int ck0 = tid, ck1 = tid + 256;
    const int r0c = ck0 >> 2, c0c = (ck0 & 3) * 8;
    const int r1c = ck1 >> 2, c1c = (ck1 & 3) * 8;

    const int lmat = lane >> 3, lrow = lane & 7;
    const uint32_t a_lane_off = (uint32_t)(((lmat & 1) * 8 + lrow) * LDSB + (lmat >> 1) * 8) * 2;
    const uint32_t b_lane_off = (uint32_t)(((lmat >> 1) * 8 + lrow) * LDSB + (lmat & 1) * 8) * 2;

    auto cpStage = [&](int c, int st){
        int kc = c * BKC;
        uint32_t base = sb + (uint32_t)(st * STGE) * 2;
        uint32_t so0 = (uint32_t)(r0c * LDSB + c0c) * 2;
        uint32_t so1 = (uint32_t)(r1c * LDSB + c1c) * 2;
        cp16(base + so0,            sl.Ah + (size_t)(row0 + r0c) * lda + kc + c0c);
        cp16(base + so1,            sl.Ah + (size_t)(row0 + r1c) * lda + kc + c1c);
        cp16(base + ARRE*2 + so0,   sl.Al + (size_t)(row0 + r0c) * lda + kc + c0c);
        cp16(base + ARRE*2 + so1,   sl.Al + (size_t)(row0 + r1c) * lda + kc + c1c);
        cp16(base + ARRE*4 + so0,   sl.Bh + (size_t)(col0 + r0c) * ldb + kc + c0c);
        cp16(base + ARRE*4 + so1,   sl.Bh + (size_t)(col0 + r1c) * ldb + kc + c1c);
        asm volatile("cp.async.commit_group;" ::: "memory");
    };

    cpStage(0, 0);
    if (NC > 1) cpStage(1, 1);
    else asm volatile("cp.async.commit_group;" ::: "memory");

    for (int c = 0; c < NC; c++) {
        const int st = c & 1;
        if (c + 2 < NC) asm volatile("cp.async.wait_group 1;" ::: "memory");
        else            asm volatile("cp.async.wait_group 0;" ::: "memory");
        __syncthreads();

        const uint32_t sA_h = sb + (uint32_t)(st*STGE) * 2;
        const uint32_t sA_l = sA_h + ARRE*2;
        const uint32_t sB_h = sA_h + ARRE*4;

        #pragma unroll
        for (int kk = 0; kk < 2; kk++) {
            const uint32_t kbo = (uint32_t)(kk * 16) * 2;
            uint32_t bh[4][2];
            #pragma unroll
            for (int pr = 0; pr < 2; pr++) {
                uint32_t nbase = (uint32_t)((wn*32 + pr*16) * LDSB) * 2;
                uint32_t r4[4];
                ldsm_x4(r4, sB_h + nbase + kbo + b_lane_off);
                bh[pr*2][0] = r4[0]; bh[pr*2][1] = r4[1];
                bh[pr*2+1][0] = r4[2]; bh[pr*2+1][1] = r4[3];
            }
            #pragma unroll
            for (int mi = 0; mi < 4; mi++) {
                uint32_t rbase = (uint32_t)((wm*64 + mi*16) * LDSB) * 2;
                uint32_t ah[4], al[4];
                ldsm_x4(ah, sA_h + rbase + kbo + a_lane_off);
                ldsm_x4(al, sA_l + rbase + kbo + a_lane_off);
                #pragma unroll
                for (int ni = 0; ni < 4; ni++) {
                    mma16816h(acc[mi][ni], ah, bh[ni]);
                    mma16816h(acc[mi][ni], al, bh[ni]);
                }
            }
        }
        __syncthreads();
        if (c + 2 < NC) cpStage(c + 2, st);
    }

    #pragma unroll
    for (int mi = 0; mi < 4; mi++) {
        #pragma unroll
        for (int ni = 0; ni < 4; ni++) {
            int r1 = row0 + wm*64 + mi*16 + g8;
            int c1 = col0 + wn*32 + ni*8 + tig*2;
            #pragma unroll
            for (int q = 0; q < 4; q++) {
                int r = (q < 2) ? r1 : r1 + 8;
                int cc = c1 + (q & 1);
                float v = acc[mi][ni][q];
                if (sl.bias) v += sl.bias[cc];
                if (sl.mode == 1)      v = fmaxf(v, 0.f);
                else if (sl.mode == 2) v = 1.f / (1.f + __expf(-v));
                if (sl.Ch) {
                    hf h, l; split2h(v, h, l);
                    sl.Ch[(size_t)r * N + cc] = h;
                    sl.Cl[(size_t)r * N + cc] = l;
                } else {
                    if (sl.res) v += sl.res[(size_t)r * N + cc];
                    sl.C[(size_t)r * N + cc] = v;
                }
            }
        }
    }
}

// ---------------- windowed attention core (batched over z) ------------------
struct AtS { const float* Q; const float* K; const float* V; const float* G;
             hf* cth; hf* ctl; };
struct AtBatch { AtS s[3]; };

__global__ void __launch_bounds__(256)
attn_core_kernel(AtBatch ab, const unsigned char* __restrict__ mask)
{
    AtS sl = ab.s[blockIdx.y];
    int idx  = blockIdx.x * blockDim.x + threadIdx.x;
    int gw   = idx >> 5;
    int lane = idx & 31;
    int s = gw & (SS - 1);
    int h = (gw >> 10) & (HH - 1);
    int n = gw >> 12;

    int base_q = (n * SS + s) * DD + h * CC;
    float q0 = sl.Q[base_q + lane];
    float q1 = sl.Q[base_q + 32 + lane];

    int t0 = s - WINSZ; if (t0 < 0) t0 = 0;
    int t1 = s + WINSZ; if (t1 > SS - 1) t1 = SS - 1;
    int cnt = t1 - t0 + 1;

    float sc[2 * WINSZ + 1];
    float mx = -1e30f;
    for (int i = 0; i < cnt; i++) {
        int t = t0 + i;
        float v;
        if (mask[n * SS + t]) v = -1e30f;
        else {
            int bk = (n * SS + t) * DD + h * CC;
            float p = q0 * sl.K[bk + lane] + q1 * sl.K[bk + 32 + lane];
            #pragma unroll
            for (int o = 16; o > 0; o >>= 1) p += __shfl_xor_sync(0xffffffffu, p, o);
            v = p * 0.125f;
        }
        sc[i] = v;
        mx = fmaxf(mx, v);
    }
    float denom = 0.f;
    for (int i = 0; i < cnt; i++) {
        float e = (sc[i] <= -1e29f) ? 0.f : __expf(sc[i] - mx);
        sc[i] = e; denom += e;
    }
    float inv = (denom > 0.f) ? (1.f / denom) : 0.f;
    float o0 = 0.f, o1 = 0.f;
    for (int i = 0; i < cnt; i++) {
        int bv = (n * SS + (t0 + i)) * DD + h * CC;
        float a = sc[i] * inv;
        o0 = fmaf(a, sl.V[bv + lane], o0);
        o1 = fmaf(a, sl.V[bv + 32 + lane], o1);
    }
    float v0 = o0 * sl.G[base_q + lane];
    float v1 = o1 * sl.G[base_q + 32 + lane];
    hf h0, l0, h1, l1;
    split2h(v0, h0, l0); split2h(v1, h1, l1);
    sl.cth[base_q + lane]      = h0;  sl.ctl[base_q + lane]      = l0;
    sl.cth[base_q + 32 + lane] = h1;  sl.ctl[base_q + 32 + lane] = l1;
}

// ---------------- host orchestration ----------------------------------------
extern "C" void kernel_launch(void* const* d_in, const int* in_sizes, int n_in,
                              void* d_out, int out_size)
{
    (void)in_sizes; (void)n_in; (void)out_size;
    const float* inL = (const float*)d_in[0];
    const float* inN = (const float*)d_in[1];
    const float* inO = (const float*)d_in[2];
    const unsigned char* mask = (const unsigned char*)d_in[3];
    const float* aWq = (const float*)d_in[4];
    const float* aWk = (const float*)d_in[5];
    const float* aWv = (const float*)d_in[6];
    const float* aGw = (const float*)d_in[7];
    const float* aGb = (const float*)d_in[8];
    const float* aOw = (const float*)d_in[9];
    const float* aOb = (const float*)d_in[10];
    const float* ln_g = (const float*)d_in[11];
    const float* ln_b = (const float*)d_in[12];
    const float* ff_g = (const float*)d_in[13];
    const float* ff_b = (const float*)d_in[14];
    const float* ff_w1 = (const float*)d_in[15];
    const float* ff_b1 = (const float*)d_in[16];
    const float* ff_w2 = (const float*)d_in[17];
    const float* ff_b2 = (const float*)d_in[18];

    float* L  = (float*)d_out;
    float* Nb = L + BSD;
    float* O  = Nb + BSD;
    float* X[3] = { L, Nb, O };

    cudaMemcpyAsync(L,  inL, (size_t)BSD * sizeof(float), cudaMemcpyDeviceToDevice);
    cudaMemcpyAsync(Nb, inN, (size_t)BSD * sizeof(float), cudaMemcpyDeviceToDevice);
    cudaMemcpyAsync(O,  inO, (size_t)BSD * sizeof(float), cudaMemcpyDeviceToDevice);

    void* pa;
    #define SYM(var, sym) cudaGetSymbolAddress(&pa, sym); auto var = (decltype(&sym[0]))pa;
    SYM(Qb, g_Q) SYM(Kb, g_Kb) SYM(Vb, g_Vb) SYM(Gg, g_Gb)
    SYM(lnh, g_lnh) SYM(lnl, g_lnl)
    SYM(cth, g_cth) SYM(ctl, g_ctl)
    SYM(hidh, g_hidh) SYM(hidl, g_hidl)
    SYM(b56, g_b56) SYM(part, g_part)
    SYM(wq, g_WqT) SYM(wk, g_WkT) SYM(wv, g_WvT) SYM(gw, g_GwT) SYM(ow, g_OwT)
    SYM(w1, g_w1T) SYM(w2, g_w2T)
    #undef SYM

    cudaFuncSetAttribute(gemm_batched, cudaFuncAttributeMaxDynamicSharedMemorySize, GSMEM);

    // ---- weight prep: 4 launches ----
    {
        WsAll wa;
        wa.src[0]=aWq; wa.src[1]=aWk; wa.src[2]=aWv; wa.src[3]=aGw; wa.src[4]=aOw;
        wa.th[0]=wq; wa.th[1]=wk; wa.th[2]=wv; wa.th[3]=gw; wa.th[4]=ow;
        wsplit_all<<<dim3(8, 8, 35), 256>>>(wa);
        wsplit_big<<<dim3(HID/32, DD/32, 6), 256>>>(ff_w1, w1, DD, HID,
                                                    (long long)DD*HID, (long long)DD*HID);
        wsplit_big<<<dim3(DD/32, HID/32, 6), 256>>>(ff_w2, w2, HID, DD,
                                                    (long long)HID*DD, (long long)HID*DD);
        b56_kernel<<<1, DD>>>(aOb);
    }

    float* QKVG[4] = { Qb, Kb, Vb, Gg };

    auto run_ln = [&](int nz, const float* xs[], const float* gbase, const float* bbase,
                      const int* ks, const int* slots) {
        LnBatch lb;
        for (int j = 0; j < nz; j++)
            lb.s[j] = { xs[j], gbase + (size_t)ks[j]*DD, bbase + (size_t)ks[j]*DD,
                        lnh + (size_t)slots[j]*BSD, lnl + (size_t)slots[j]*BSD };
        ln_kernel<<<dim3(MM, nz), 256>>>(lb);
    };

    auto run_qkvg = [&](int nz, const int* mods, const int* qslot, const int* kvslot) {
        Batch bt = {};
        for (int j = 0; j < nz; j++) {
            int k = mods[j];
            for (int c = 0; c < 4; c++) {
                Slice& s = bt.s[j*4 + c];
                int slot = (c == 0) ? qslot[j] : kvslot[j];
                s.Ah = lnh + (size_t)slot*BSD;
                s.Al = lnl + (size_t)slot*BSD;
                const hf* bh[4] = { wq, wk, wv, gw };
                s.Bh = bh[c] + (size_t)k*DD*DD;
                s.bias = (c == 3) ? (aGb + (size_t)k*DD) : nullptr;
                s.C = QKVG[c] + (size_t)j*BSD;
                s.mode = (c == 3) ? 2 : 0;
                s.lda = DD; s.ldb = DD; s.Ksub = DD;
            }
        }
        gemm_batched<<<dim3(DD/128, MM/128, nz*4), 256, GSMEM>>>(bt, MM, DD);
    };

    auto run_attn = [&](int nz) {
        AtBatch ab = {};
        for (int j = 0; j < nz; j++)
            ab.s[j] = { Qb + (size_t)j*BSD, Kb + (size_t)j*BSD, Vb + (size_t)j*BSD,
                        Gg + (size_t)j*BSD, cth + (size_t)j*BSD, ctl + (size_t)j*BSD };
        attn_core_kernel<<<dim3((BB*HH*SS*32)/256, nz), 256>>>(ab, mask);
    };

    auto run_proj = [&](int nz, const int* mods, float* const* dst) {
        Batch bt = {};
        for (int j = 0; j < nz; j++) {
            int k = mods[j];
            Slice& s = bt.s[j];
            s.Ah = cth + (size_t)j*BSD;
            s.Al = ctl + (size_t)j*BSD;
            s.Bh = ow + (size_t)k*DD*DD;
            s.bias = aOb + (size_t)k*DD;
            s.res = dst[j]; s.C = dst[j];
            s.lda = DD; s.ldb = DD; s.Ksub = DD;
        }
        gemm_batched<<<dim3(DD/128, MM/128, nz), 256, GSMEM>>>(bt, MM, DD);
    };

    auto run_ff = [&](int nz, const int* mods, float* const* dst) {
        LnBatch lb;
        for (int j = 0; j < nz; j++)
            lb.s[j] = { dst[j], ff_g + (size_t)mods[j]*DD, ff_b + (size_t)mods[j]*DD,
                        lnh + (size_t)j*BSD, lnl + (size_t)j*BSD };
        ln_kernel<<<dim3(MM, nz), 256>>>(lb);
        Batch b1 = {};
        for (int j = 0; j < nz; j++) {
            Slice& s = b1.s[j];
            s.Ah = lnh + (size_t)j*BSD; s.Al = lnl + (size_t)j*BSD;
            s.Bh = w1 + (size_t)mods[j]*DD*HID;
            s.bias = ff_b1 + (size_t)mods[j]*HID;
            s.Ch = hidh + (size_t)j*MH; s.Cl = hidl + (size_t)j*MH;
            s.mode = 1; s.lda = DD; s.ldb = DD; s.Ksub = DD;
        }
        gemm_batched<<<dim3(HID/128, MM/128, nz), 256, GSMEM>>>(b1, MM, HID);
        Batch b2 = {};
        for (int j = 0; j < nz; j++)
            for (int sp = 0; sp < 4; sp++) {
                Slice& s = b2.s[j*4 + sp];
                s.Ah = hidh + (size_t)j*MH + sp*512;
                s.Al = hidl + (size_t)j*MH + sp*512;
                s.Bh = w2 + (size_t)mods[j]*HID*DD + sp*512;
                s.C = part + (size_t)(j*4 + sp)*MD;
                s.lda = HID; s.ldb = HID; s.Ksub = 512;
            }
        gemm_batched<<<dim3(DD/128, MM/128, nz*4), 256, GSMEM>>>(b2, MM, DD);
        RdBatch rb = {};
        for (int j = 0; j < nz; j++)
            rb.s[j] = { part + (size_t)j*4*MD, ff_b2 + (size_t)mods[j]*DD,
                        dst[j], dst[j], 4 };
        reduce_kernel<<<dim3((int)(MD/1024), nz), 256>>>(rb);
    };

    for (int it = 0; it < NITER; it++) {
        // -------- Phase 1: self blocks --------
        {
            const float* xs[3] = { L, Nb, O };
            const int lnk[3] = { 0, 1, 2 };
            const int slots[3] = { 0, 1, 2 };
            run_ln(3, xs, ln_g, ln_b, lnk, slots);
            const int mods[3] = { 0, 1, 2 };
            run_qkvg(3, mods, slots, slots);
            run_attn(3);
            run_proj(3, mods, X);
            run_ff(3, mods, X);
        }
        // -------- Phase 2: cross blocks --------
        {
            const float* xs[3] = { O, L, Nb };
            const int lnk[3] = { 3, 4, 5 };
            const int slots[3] = { 3, 0, 1 };
            run_ln(3, xs, ln_g, ln_b, lnk, slots);
            const int mods[2] = { 3, 4 };
            const int qslot[2] = { 0, 1 };
            const int kvslot[2] = { 3, 3 };
            run_qkvg(2, mods, qslot, kvslot);
            run_attn(2);
            float* dst[2] = { L, Nb };
            run_proj(2, mods, dst);
            run_ff(2, mods, dst);
        }
        // -------- Phase 3: O update --------
        {
            const float* xs[3] = { L, Nb, O };
            const int lnk[3] = { 6, 7, 8 };
            const int slots[3] = { 0, 1, 2 };
            run_ln(3, xs, ln_g, ln_b, lnk, slots);
            const int mods[2] = { 5, 6 };
            const int qslot[2] = { 2, 2 };
            const int kvslot[2] = { 1, 0 };
            run_qkvg(2, mods, qslot, kvslot);
            run_attn(2);
            Batch bp = {};
            for (int sp = 0; sp < 2; sp++) {
                Slice& s = bp.s[sp];
                s.Ah = cth + (size_t)sp*BSD;
                s.Al = ctl + (size_t)sp*BSD;
                s.Bh = ow + (size_t)(5 + sp)*DD*DD;
                s.C = part + (size_t)sp*MD;
                s.lda = DD; s.ldb = DD; s.Ksub = DD;
            }
            gemm_batched<<<dim3(DD/128, MM/128, 2), 256, GSMEM>>>(bp, MM, DD);
            RdBatch rp = {};
            rp.s[0] = { part, b56, O, O, 2 };
            reduce_kernel<<<dim3((int)(MD/1024), 1), 256>>>(rp);
            const int ffm[1] = { 5 };
            float* dst[1] = { O };
            run_ff(1, ffm, dst);
        }
    }
}

// round 12
// speedup vs baseline: 1.1113x; 1.1113x over previous
#include <cuda_runtime.h>
#include <cuda_bf16.h>
#include <stdint.h>
#include <math.h>

#define BB 2
#define SS 1024
#define DD 256
#define HH 4
#define CC 64
#define WINSZ 10
#define NITER 2
#define MM 2048
#define HID 2048
#define BSD (BB*SS*DD)
#define MH ((size_t)MM*HID)
#define MD ((size_t)MM*DD)

typedef __nv_bfloat16 bf16;

// ---------------- scratch (device globals; no allocation) -------------------
__device__ float g_Q[3*BSD], g_Kb[3*BSD], g_Vb[3*BSD], g_Gb[3*BSD];
__device__ float g_b56[DD];
__device__ float g_part[12*MD];
__device__ bf16 g_lnh[7*BSD], g_lnl[7*BSD];          // 7 LN slots
__device__ bf16 g_cth[3*BSD], g_ctl[3*BSD];
__device__ bf16 g_hidh[3*MH], g_hidl[3*MH];

__device__ bf16 g_WqTh[7*DD*DD], g_WqTl[7*DD*DD];
__device__ bf16 g_WkTh[7*DD*DD], g_WkTl[7*DD*DD];
__device__ bf16 g_WvTh[7*DD*DD], g_WvTl[7*DD*DD];
__device__ bf16 g_GwTh[7*DD*DD], g_GwTl[7*DD*DD];
__device__ bf16 g_OwTh[7*DD*DD], g_OwTl[7*DD*DD];
__device__ bf16 g_w1Th[(size_t)6*DD*HID], g_w1Tl[(size_t)6*DD*HID];
__device__ bf16 g_w2Th[(size_t)6*HID*DD], g_w2Tl[(size_t)6*HID*DD];

__device__ __forceinline__ void split2(float v, bf16& h, bf16& l){
    h = __float2bfloat16(v);
    l = __float2bfloat16(v - __bfloat162float(h));
}
__device__ __forceinline__ uint32_t smem_u32(const void* p){
    uint32_t a;
    asm("{ .reg .u64 t; cvta.to.shared.u64 t, %1; cvt.u32.u64 %0, t; }" : "=r"(a) : "l"(p));
    return a;
}
__device__ __forceinline__ void cp16(uint32_t saddr, const void* g){
    asm volatile("cp.async.cg.shared.global [%0], [%1], 16;" :: "r"(saddr), "l"(g));
}
__device__ __forceinline__ void ldsm_x4(uint32_t* r, uint32_t addr){
    asm volatile("ldmatrix.sync.aligned.m8n8.x4.shared.b16 {%0,%1,%2,%3}, [%4];"
        : "=r"(r[0]), "=r"(r[1]), "=r"(r[2]), "=r"(r[3]) : "r"(addr));
}

// ---------------- weight transpose + split ----------------------------------
__device__ __forceinline__ void wsplit_body(
    const float* w, bf16* th, bf16* tl, int N, int ldt)
{
    __shared__ float sm[32][33];
    int n0 = blockIdx.x * 32, k0 = blockIdx.y * 32;
    int tx = threadIdx.x & 31, ty = threadIdx.x >> 5;
    #pragma unroll
    for (int i = 0; i < 4; i++)
        sm[ty + i*8][tx] = w[(size_t)(k0 + ty + i*8) * N + n0 + tx];
    __syncthreads();
    #pragma unroll
    for (int i = 0; i < 4; i++) {
        int n = n0 + ty + i*8;
        bf16 h, l; split2(sm[tx][ty + i*8], h, l);
        th[(size_t)n * ldt + k0 + tx] = h;
        tl[(size_t)n * ldt + k0 + tx] = l;
    }
}

struct WsAll { const float* src[5]; bf16* th[5]; bf16* tl[5]; const float* aOb; };
// z 0..34: fam*7+module slices; z==35: b56
__global__ void __launch_bounds__(256) wsplit_all(WsAll wa)
{
    if (blockIdx.z == 35) {
        if (blockIdx.x == 0 && blockIdx.y == 0 && threadIdx.x < DD)
            g_b56[threadIdx.x] = wa.aOb[5*DD + threadIdx.x] + wa.aOb[6*DD + threadIdx.x];
        return;
    }
    int fam = blockIdx.z / 7, mod = blockIdx.z % 7;
    wsplit_body(wa.src[fam] + (size_t)mod*DD*DD,
                wa.th[fam] + (size_t)mod*DD*DD, wa.tl[fam] + (size_t)mod*DD*DD,
                DD, DD);
}
__global__ void __launch_bounds__(256) wsplit_big(
    const float* __restrict__ W, bf16* __restrict__ Th, bf16* __restrict__ Tl,
    int K, int N, long long wstride, long long tstride)
{
    wsplit_body(W + (size_t)blockIdx.z * wstride,
                Th + (size_t)blockIdx.z * tstride, Tl + (size_t)blockIdx.z * tstride,
                N, K);
}

// ---------------- row stats helper (256 threads, 8 warps) -------------------
__device__ __forceinline__ void row_stats(float v, float& mean, float& rstd,
                                          float* red, float* sh)
{
    int t = threadIdx.x;
    float s = v;
    #pragma unroll
    for (int o = 16; o > 0; o >>= 1) s += __shfl_xor_sync(0xffffffffu, s, o);
    if ((t & 31) == 0) red[t >> 5] = s;
    __syncthreads();
    if (t == 0) { float tot=0.f; for (int i=0;i<8;i++) tot+=red[i]; sh[0] = tot*(1.0f/DD); }
    __syncthreads();
    mean = sh[0];
    float d = v - mean;
    s = d * d;
    #pragma unroll
    for (int o = 16; o > 0; o >>= 1) s += __shfl_xor_sync(0xffffffffu, s, o);
    if ((t & 31) == 0) red[t >> 5] = s;
    __syncthreads();
    if (t == 0) { float tot=0.f; for (int i=0;i<8;i++) tot+=red[i]; sh[1] = rsqrtf(tot*(1.0f/DD)+1e-5f); }
    __syncthreads();
    rstd = sh[1];
}

// ---------------- standalone LayerNorm (batched over z) ---------------------
struct LnS { const float* x; const float* g; const float* b; bf16* oh; bf16* ol; };
struct LnBatch { LnS s[3]; };

__global__ void __launch_bounds__(256) ln_kernel(LnBatch lb)
{
    LnS sl = lb.s[blockIdx.y];
    int row = blockIdx.x, t = threadIdx.x;
    float v = sl.x[(size_t)row * DD + t];
    __shared__ float red[8]; __shared__ float sh[2];
    float mean, rstd;
    row_stats(v, mean, rstd, red, sh);
    float out = (v - mean) * rstd * sl.g[t] + sl.b[t];
    bf16 h, l; split2(out, h, l);
    sl.oh[(size_t)row * DD + t] = h;
    sl.ol[(size_t)row * DD + t] = l;
}

// ---------------- fused split-K reduce + LN(s) -------------------------------
// dst = sum(partials) + bias + res;  then up to 2 LNs of dst (shared stats)
struct FRdS {
    const float* p; const float* bias; const float* res; float* dst; int nsplit;
    int nln;
    const float *lg0, *lb0; bf16 *oh0, *ol0;
    const float *lg1, *lb1; bf16 *oh1, *ol1;
};
struct FRdBatch { FRdS s[3]; };

__global__ void __launch_bounds__(256) fused_reduce_ln(FRdBatch rb)
{
    FRdS sl = rb.s[blockIdx.y];
    int row = blockIdx.x, t = threadIdx.x;
    size_t idx = (size_t)row * DD + t;
    float a = sl.p[idx];
    for (int s = 1; s < sl.nsplit; s++) a += sl.p[(size_t)s * MD + idx];
    a += sl.bias[t];
    if (sl.res) a += sl.res[idx];
    sl.dst[idx] = a;

    __shared__ float red[8]; __shared__ float sh[2];
    float mean, rstd;
    row_stats(a, mean, rstd, red, sh);
    float nrm = (a - mean) * rstd;
    {
        float out = nrm * sl.lg0[t] + sl.lb0[t];
        bf16 h, l; split2(out, h, l);
        sl.oh0[idx] = h; sl.ol0[idx] = l;
    }
    if (sl.nln > 1) {
        float out = nrm * sl.lg1[t] + sl.lb1[t];
        bf16 h, l; split2(out, h, l);
        sl.oh1[idx] = h; sl.ol1[idx] = l;
    }
}

// ---------------- batched split-compensated MMA GEMM ------------------------
struct Slice {
    const bf16 *Ah, *Al, *Bh, *Bl;
    const float *bias, *res;
    float* C; bf16 *Ch, *Cl;
    int mode, lda, ldb, Ksub;
};
struct Batch { Slice s[12]; };

#define BKC 32
#define LDSB 40
#define ARRE (128*LDSB)
#define STGE (4*ARRE)
#define GSMEM (2*STGE*2)

__device__ __forceinline__ void mma16816(float* c, const uint32_t* a, const uint32_t* b){
    asm volatile("mma.sync.aligned.m16n8k16.row.col.f32.bf16.bf16.f32 "
        "{%0,%1,%2,%3}, {%4,%5,%6,%7}, {%8,%9}, {%0,%1,%2,%3};"
        : "+f"(c[0]), "+f"(c[1]), "+f"(c[2]), "+f"(c[3])
        : "r"(a[0]), "r"(a[1]), "r"(a[2]), "r"(a[3]), "r"(b[0]), "r"(b[1]));
}

__global__ void __launch_bounds__(256,2)
gemm_batched(Batch bt, int M, int N)
{
    extern __shared__ __align__(16) bf16 smem[];
    const Slice sl = bt.s[blockIdx.z];
    const int tid  = threadIdx.x;
    const int warp = tid >> 5, lane = tid & 31;
    const int wm = warp >> 2, wn = warp & 3;
    const int row0 = blockIdx.y * 128, col0 = blockIdx.x * 128;
    const int g8 = lane >> 2, tig = lane & 3;
    const uint32_t sb = smem_u32(smem);
    const int NC = sl.Ksub / BKC;
    const int lda = sl.lda, ldb = sl.ldb;

    float acc[4][4][4];
    #pragma unroll
    for (int i=0;i<4;i++) for (int j=0;j<4;j++) for (int q=0;q<4;q++) acc[i][j][q]=0.f;

    const int ck0 = tid, ck1 = tid + 256;
    const int r0c = ck0 >> 2, c0c = (ck0 & 3) * 8;
    const int r1c = ck1 >> 2, c1c = (ck1 & 3) * 8;

    const int lmat = lane >> 3, lrow = lane & 7;
    const uint32_t a_lane_off = (uint32_t)(((lmat & 1) * 8 + lrow) * LDSB + (lmat >> 1) * 8) * 2;
    const uint32_t b_lane_off = (uint32_t)(((lmat >> 1) * 8 + lrow) * LDSB + (lmat & 1) * 8) * 2;

    auto cpStage = [&](int c, int st){
        int kc = c * BKC;
        uint32_t base = sb + (uint32_t)(st * STGE) * 2;
        uint32_t so0 = (uint32_t)(r0c * LDSB + c0c) * 2;
        uint32_t so1 = (uint32_t)(r1c * LDSB + c1c) * 2;
        cp16(base + so0,            sl.Ah + (size_t)(row0 + r0c) * lda + kc + c0c);
        cp16(base + so1,            sl.Ah + (size_t)(row0 + r1c) * lda + kc + c1c);
        cp16(base + ARRE*2 + so0,   sl.Al + (size_t)(row0 + r0c) * lda + kc + c0c);
        cp16(base + ARRE*2 + so1,   sl.Al + (size_t)(row0 + r1c) * lda + kc + c1c);
        cp16(base + ARRE*4 + so0,   sl.Bh + (size_t)(col0 + r0c) * ldb + kc + c0c);
        cp16(base + ARRE*4 + so1,   sl.Bh + (size_t)(col0 + r1c) * ldb + kc + c1c);
        cp16(base + ARRE*6 + so0,   sl.Bl + (size_t)(col0 + r0c) * ldb + kc + c0c);
        cp16(base + ARRE*6 + so1,   sl.Bl + (size_t)(col0 + r1c) * ldb + kc + c1c);
        asm volatile("cp.async.commit_group;" ::: "memory");
    };

    cpStage(0, 0);
    if (NC > 1) cpStage(1, 1);
    else asm volatile("cp.async.commit_group;" ::: "memory");

    for (int c = 0; c < NC; c++) {
        const int st = c & 1;
        if (c + 2 < NC) asm volatile("cp.async.wait_group 1;" ::: "memory");
        else            asm volatile("cp.async.wait_group 0;" ::: "memory");
        __syncthreads();

        const uint32_t sA_h = sb + (uint32_t)(st*STGE) * 2;
        const uint32_t sA_l = sA_h + ARRE*2;
        const uint32_t sB_h = sA_h + ARRE*4;
        const uint32_t sB_l = sA_h + ARRE*6;

        #pragma unroll
        for (int kk = 0; kk < 2; kk++) {
            const uint32_t kbo = (uint32_t)(kk * 16) * 2;
            uint32_t bh[4][2], bl[4][2];
            #pragma unroll
            for (int pr = 0; pr < 2; pr++) {
                uint32_t nbase = (uint32_t)((wn*32 + pr*16) * LDSB) * 2;
                uint32_t r4[4];
                ldsm_x4(r4, sB_h + nbase + kbo + b_lane_off);
                bh[pr*2][0] = r4[0]; bh[pr*2][1] = r4[1];
                bh[pr*2+1][0] = r4[2]; bh[pr*2+1][1] = r4[3];
                ldsm_x4(r4, sB_l + nbase + kbo + b_lane_off);
                bl[pr*2][0] = r4[0]; bl[pr*2][1] = r4[1];
                bl[pr*2+1][0] = r4[2]; bl[pr*2+1][1] = r4[3];
            }
            #pragma unroll
            for (int mi = 0; mi < 4; mi++) {
                uint32_t rbase = (uint32_t)((wm*64 + mi*16) * LDSB) * 2;
                uint32_t ah[4], al[4];
                ldsm_x4(ah, sA_h + rbase + kbo + a_lane_off);
                ldsm_x4(al, sA_l + rbase + kbo + a_lane_off);
                #pragma unroll
                for (int ni = 0; ni < 4; ni++) {
                    mma16816(acc[mi][ni], ah, bh[ni]);
                    mma16816(acc[mi][ni], ah, bl[ni]);
                    mma16816(acc[mi][ni], al, bh[ni]);
                }
            }
        }
        __syncthreads();
        if (c + 2 < NC) cpStage(c + 2, st);
    }

    #pragma unroll
    for (int mi = 0; mi < 4; mi++) {
        #pragma unroll
        for (int ni = 0; ni < 4; ni++) {
            int r1 = row0 + wm*64 + mi*16 + g8;
            int c1 = col0 + wn*32 + ni*8 + tig*2;
            #pragma unroll
            for (int q = 0; q < 4; q++) {
                int r = (q < 2) ? r1 : r1 + 8;
                int cc = c1 + (q & 1);
                float v = acc[mi][ni][q];
                if (sl.bias) v += sl.bias[cc];
                if (sl.mode == 1)      v = fmaxf(v, 0.f);
                else if (sl.mode == 2) v = 1.f / (1.f + __expf(-v));
                if (sl.Ch) {
                    bf16 h, l; split2(v, h, l);
                    sl.Ch[(size_t)r * N + cc] = h;
                    sl.Cl[(size_t)r * N + cc] = l;
                } else {
                    if (sl.res) v += sl.res[(size_t)r * N + cc];
                    sl.C[(size_t)r * N + cc] = v;
                }
            }
        }
    }
}

// ---------------- windowed attention core (batched over z) ------------------
struct AtS { const float* Q; const float* K; const float* V; const float* G;
             bf16* cth; bf16* ctl; };
struct AtBatch { AtS s[3]; };

__global__ void __launch_bounds__(256)
attn_core_kernel(AtBatch ab, const unsigned char* __restrict__ mask)
{
    AtS sl = ab.s[blockIdx.y];
    int idx  = blockIdx.x * blockDim.x + threadIdx.x;
    int gw   = idx >> 5;
    int lane = idx & 31;
    int s = gw & (SS - 1);
    int h = (gw >> 10) & (HH - 1);
    int n = gw >> 12;

    int base_q = (n * SS + s) * DD + h * CC;
    float q0 = sl.Q[base_q + lane];
    float q1 = sl.Q[base_q + 32 + lane];

    int t0 = s - WINSZ; if (t0 < 0) t0 = 0;
    int t1 = s + WINSZ; if (t1 > SS - 1) t1 = SS - 1;
    int cnt = t1 - t0 + 1;

    float sc[2 * WINSZ + 1];
    float mx = -1e30f;
    for (int i = 0; i < cnt; i++) {
        int t = t0 + i;
        float v;
        if (mask[n * SS + t]) v = -1e30f;
        else {
            int bk = (n * SS + t) * DD + h * CC;
            float p = q0 * sl.K[bk + lane] + q1 * sl.K[bk + 32 + lane];
            #pragma unroll
            for (int o = 16; o > 0; o >>= 1) p += __shfl_xor_sync(0xffffffffu, p, o);
            v = p * 0.125f;
        }
        sc[i] = v;
        mx = fmaxf(mx, v);
    }
    float denom = 0.f;
    for (int i = 0; i < cnt; i++) {
        float e = (sc[i] <= -1e29f) ? 0.f : __expf(sc[i] - mx);
        sc[i] = e; denom += e;
    }
    float inv = (denom > 0.f) ? (1.f / denom) : 0.f;
    float o0 = 0.f, o1 = 0.f;
    for (int i = 0; i < cnt; i++) {
        int bv = (n * SS + (t0 + i)) * DD + h * CC;
        float a = sc[i] * inv;
        o0 = fmaf(a, sl.V[bv + lane], o0);
        o1 = fmaf(a, sl.V[bv + 32 + lane], o1);
    }
    float v0 = o0 * sl.G[base_q + lane];
    float v1 = o1 * sl.G[base_q + 32 + lane];
    bf16 h0, l0, h1, l1;
    split2(v0, h0, l0); split2(v1, h1, l1);
    sl.cth[base_q + lane]      = h0;  sl.ctl[base_q + lane]      = l0;
    sl.cth[base_q + 32 + lane] = h1;  sl.ctl[base_q + 32 + lane] = l1;
}

// ---------------- host orchestration ----------------------------------------
extern "C" void kernel_launch(void* const* d_in, const int* in_sizes, int n_in,
                              void* d_out, int out_size)
{
    (void)in_sizes; (void)n_in; (void)out_size;
    const float* inL = (const float*)d_in[0];
    const float* inN = (const float*)d_in[1];
    const float* inO = (const float*)d_in[2];
    const unsigned char* mask = (const unsigned char*)d_in[3];
    const float* aWq = (const float*)d_in[4];
    const float* aWk = (const float*)d_in[5];
    const float* aWv = (const float*)d_in[6];
    const float* aGw = (const float*)d_in[7];
    const float* aGb = (const float*)d_in[8];
    const float* aOw = (const float*)d_in[9];
    const float* aOb = (const float*)d_in[10];
    const float* ln_g = (const float*)d_in[11];
    const float* ln_b = (const float*)d_in[12];
    const float* ff_g = (const float*)d_in[13];
    const float* ff_b = (const float*)d_in[14];
    const float* ff_w1 = (const float*)d_in[15];
    const float* ff_b1 = (const float*)d_in[16];
    const float* ff_w2 = (const float*)d_in[17];
    const float* ff_b2 = (const float*)d_in[18];

    float* L  = (float*)d_out;
    float* Nb = L + BSD;
    float* O  = Nb + BSD;
    float* X[3] = { L, Nb, O };

    cudaMemcpyAsync(L,  inL, (size_t)BSD * sizeof(float), cudaMemcpyDeviceToDevice);
    cudaMemcpyAsync(Nb, inN, (size_t)BSD * sizeof(float), cudaMemcpyDeviceToDevice);
    cudaMemcpyAsync(O,  inO, (size_t)BSD * sizeof(float), cudaMemcpyDeviceToDevice);

    void* pa;
    #define SYM(var, sym) cudaGetSymbolAddress(&pa, sym); auto var = (decltype(&sym[0]))pa;
    SYM(Qb, g_Q) SYM(Kb, g_Kb) SYM(Vb, g_Vb) SYM(Gg, g_Gb)
    SYM(lnh, g_lnh) SYM(lnl, g_lnl)
    SYM(cth, g_cth) SYM(ctl, g_ctl)
    SYM(hidh, g_hidh) SYM(hidl, g_hidl)
    SYM(b56, g_b56) SYM(part, g_part)
    SYM(wqh, g_WqTh) SYM(wql, g_WqTl) SYM(wkh, g_WkTh) SYM(wkl, g_WkTl)
    SYM(wvh, g_WvTh) SYM(wvl, g_WvTl) SYM(gwh, g_GwTh) SYM(gwl, g_GwTl)
    SYM(owh, g_OwTh) SYM(owl, g_OwTl)
    SYM(w1h, g_w1Th) SYM(w1l, g_w1Tl) SYM(w2h, g_w2Th) SYM(w2l, g_w2Tl)
    #undef SYM

    cudaFuncSetAttribute(gemm_batched, cudaFuncAttributeMaxDynamicSharedMemorySize, GSMEM);

    // ---- weight prep: 3 launches ----
    {
        WsAll wa;
        wa.src[0]=aWq; wa.src[1]=aWk; wa.src[2]=aWv; wa.src[3]=aGw; wa.src[4]=aOw;
        wa.th[0]=wqh; wa.th[1]=wkh; wa.th[2]=wvh; wa.th[3]=gwh; wa.th[4]=owh;
        wa.tl[0]=wql; wa.tl[1]=wkl; wa.tl[2]=wvl; wa.tl[3]=gwl; wa.tl[4]=owl;
        wa.aOb = aOb;
        wsplit_all<<<dim3(8, 8, 36), 256>>>(wa);
        wsplit_big<<<dim3(HID/32, DD/32, 6), 256>>>(ff_w1, w1h, w1l, DD, HID,
                                                    (long long)DD*HID, (long long)DD*HID);
        wsplit_big<<<dim3(DD/32, HID/32, 6), 256>>>(ff_w2, w2h, w2l, HID, DD,
                                                    (long long)HID*DD, (long long)HID*DD);
    }

    float* QKVG[4] = { Qb, Kb, Vb, Gg };
    auto LS = [&](int slot) { return lnh + (size_t)slot*BSD; };
    auto LSl = [&](int slot) { return lnl + (size_t)slot*BSD; };

    auto run_ln = [&](int nz, const float* xs[], const float* gbase, const float* bbase,
                      const int* ks, const int* slots) {
        LnBatch lb;
        for (int j = 0; j < nz; j++)
            lb.s[j] = { xs[j], gbase + (size_t)ks[j]*DD, bbase + (size_t)ks[j]*DD,
                        LS(slots[j]), LSl(slots[j]) };
        ln_kernel<<<dim3(MM, nz), 256>>>(lb);
    };

    auto run_qkvg = [&](int nz, const int* mods, const int* qslot, const int* kvslot) {
        Batch bt = {};
        for (int j = 0; j < nz; j++) {
            int k = mods[j];
            for (int c = 0; c < 4; c++) {
                Slice& s = bt.s[j*4 + c];
                int slot = (c == 0) ? qslot[j] : kvslot[j];
                s.Ah = LS(slot); s.Al = LSl(slot);
                const bf16* bh[4] = { wqh, wkh, wvh, gwh };
                const bf16* bl[4] = { wql, wkl, wvl, gwl };
                s.Bh = bh[c] + (size_t)k*DD*DD;
                s.Bl = bl[c] + (size_t)k*DD*DD;
                s.bias = (c == 3) ? (aGb + (size_t)k*DD) : nullptr;
                s.C = QKVG[c] + (size_t)j*BSD;
                s.mode = (c == 3) ? 2 : 0;
                s.lda = DD; s.ldb = DD; s.Ksub = DD;
            }
        }
        gemm_batched<<<dim3(DD/128, MM/128, nz*4), 256, GSMEM>>>(bt, MM, DD);
    };

    auto run_attn = [&](int nz) {
        AtBatch ab = {};
        for (int j = 0; j < nz; j++)
            ab.s[j] = { Qb + (size_t)j*BSD, Kb + (size_t)j*BSD, Vb + (size_t)j*BSD,
                        Gg + (size_t)j*BSD, cth + (size_t)j*BSD, ctl + (size_t)j*BSD };
        attn_core_kernel<<<dim3((BB*HH*SS*32)/256, nz), 256>>>(ab, mask);
    };

    auto run_proj = [&](int nz, const int* mods, float* const* dst) {
        Batch bt = {};
        for (int j = 0; j < nz; j++) {
            int k = mods[j];
            Slice& s = bt.s[j];
            s.Ah = cth + (size_t)j*BSD;
            s.Al = ctl + (size_t)j*BSD;
            s.Bh = owh + (size_t)k*DD*DD;
            s.Bl = owl + (size_t)k*DD*DD;
            s.bias = aOb + (size_t)k*DD;
            s.res = dst[j]; s.C = dst[j];
            s.lda = DD; s.ldb = DD; s.Ksub = DD;
        }
        gemm_batched<<<dim3(DD/128, MM/128, nz), 256, GSMEM>>>(bt, MM, DD);
    };

    // FF GEMMs only (LN inputs already in lnslots); reduce launched by caller
    auto run_ff_gemms = [&](int nz, const int* mods, const int* lnslots) {
        Batch b1 = {};
        for (int j = 0; j < nz; j++) {
            Slice& s = b1.s[j];
            s.Ah = LS(lnslots[j]); s.Al = LSl(lnslots[j]);
            s.Bh = w1h + (size_t)mods[j]*DD*HID; s.Bl = w1l + (size_t)mods[j]*DD*HID;
            s.bias = ff_b1 + (size_t)mods[j]*HID;
            s.Ch = hidh + (size_t)j*MH; s.Cl = hidl + (size_t)j*MH;
            s.mode = 1; s.lda = DD; s.ldb = DD; s.Ksub = DD;
        }
        gemm_batched<<<dim3(HID/128, MM/128, nz), 256, GSMEM>>>(b1, MM, HID);
        Batch b2 = {};
        for (int j = 0; j < nz; j++)
            for (int sp = 0; sp < 4; sp++) {
                Slice& s = b2.s[j*4 + sp];
                s.Ah = hidh + (size_t)j*MH + sp*512;
                s.Al = hidl + (size_t)j*MH + sp*512;
                s.Bh = w2h + (size_t)mods[j]*HID*DD + sp*512;
                s.Bl = w2l + (size_t)mods[j]*HID*DD + sp*512;
                s.C = part + (size_t)(j*4 + sp)*MD;
                s.lda = HID; s.ldb = HID; s.Ksub = 512;
            }
        gemm_batched<<<dim3(DD/128, MM/128, nz*4), 256, GSMEM>>>(b2, MM, DD);
    };

    // initial block-LNs for iteration-1 phase 1: ln0->4, ln1->5, ln2->6
    {
        const float* xs[3] = { L, Nb, O };
        const int lnk[3] = { 0, 1, 2 };
        const int slots[3] = { 4, 5, 6 };
        run_ln(3, xs, ln_g, ln_b, lnk, slots);
    }

    for (int it = 0; it < NITER; it++) {
        // -------- Phase 1: self blocks --------
        {
            const int mods[3] = { 0, 1, 2 };
            const int slots[3] = { 4, 5, 6 };
            run_qkvg(3, mods, slots, slots);
            run_attn(3);
            run_proj(3, mods, X);
            // FF LNs (ff_g[0..2]) -> slots 0,1,2
            const float* xs[3] = { L, Nb, O };
            const int ffslots[3] = { 0, 1, 2 };
            run_ln(3, xs, ff_g, ff_b, mods, ffslots);
            run_ff_gemms(3, mods, ffslots);
            // fused reduce + next-phase LNs
            FRdBatch rb = {};
            // L: ln4 -> slot0
            rb.s[0] = { part + 0*4*MD, ff_b2 + 0*DD, L, L, 4, 1,
                        ln_g + 4*DD, ln_b + 4*DD, LS(0), LSl(0),
                        nullptr, nullptr, nullptr, nullptr };
            // N: ln5 -> slot1
            rb.s[1] = { part + 1*4*MD, ff_b2 + 1*DD, Nb, Nb, 4, 1,
                        ln_g + 5*DD, ln_b + 5*DD, LS(1), LSl(1),
                        nullptr, nullptr, nullptr, nullptr };
            // O: ln3 -> slot3, ln8 -> slot2
            rb.s[2] = { part + 2*4*MD, ff_b2 + 2*DD, O, O, 4, 2,
                        ln_g + 3*DD, ln_b + 3*DD, LS(3), LSl(3),
                        ln_g + 8*DD, ln_b + 8*DD, LS(2), LSl(2) };
            fused_reduce_ln<<<dim3(MM, 3), 256>>>(rb);
        }
        // -------- Phase 2: cross blocks --------
        {
            const int mods[2] = { 3, 4 };
            const int qslot[2] = { 0, 1 };
            const int kvslot[2] = { 3, 3 };
            run_qkvg(2, mods, qslot, kvslot);
            run_attn(2);
            float* dst[2] = { L, Nb };
            run_proj(2, mods, dst);
            const float* xs[2] = { L, Nb };
            const int ffslots[2] = { 0, 1 };
            run_ln(2, xs, ff_g, ff_b, mods, ffslots);
            run_ff_gemms(2, mods, ffslots);
            FRdBatch rb = {};
            // L: ln6 -> slot0, ln0(next) -> slot4
            rb.s[0] = { part + 0*4*MD, ff_b2 + 3*DD, L, L, 4, 2,
                        ln_g + 6*DD, ln_b + 6*DD, LS(0), LSl(0),
                        ln_g + 0*DD, ln_b + 0*DD, LS(4), LSl(4) };
            // N: ln7 -> slot1, ln1(next) -> slot5
            rb.s[1] = { part + 1*4*MD, ff_b2 + 4*DD, Nb, Nb, 4, 2,
                        ln_g + 7*DD, ln_b + 7*DD, LS(1), LSl(1),
                        ln_g + 1*DD, ln_b + 1*DD, LS(5), LSl(5) };
            fused_reduce_ln<<<dim3(MM, 2), 256>>>(rb);
        }
        // -------- Phase 3: O update --------
        {
            const int mods[2] = { 5, 6 };
            const int qslot[2] = { 2, 2 };
            const int kvslot[2] = { 1, 0 };
            run_qkvg(2, mods, qslot, kvslot);
            run_attn(2);
            // proj5 + proj6 partials
            Batch bp = {};
            for (int sp = 0; sp < 2; sp++) {
                Slice& s = bp.s[sp];
                s.Ah = cth + (size_t)sp*BSD;
                s.Al = ctl + (size_t)sp*BSD;
                s.Bh = owh + (size_t)(5 + sp)*DD*DD;
                s.Bl = owl + (size_t)(5 + sp)*DD*DD;
                s.C = part + (size_t)sp*MD;
                s.lda = DD; s.ldb = DD; s.Ksub = DD;
            }
            gemm_batched<<<dim3(DD/128, MM/128, 2), 256, GSMEM>>>(bp, MM, DD);
            // O += proj5+proj6+b56; FF5 LN -> slot0
            FRdBatch rp = {};
            rp.s[0] = { part, b56, O, O, 2, 1,
                        ff_g + 5*DD, ff_b + 5*DD, LS(0), LSl(0),
                        nullptr, nullptr, nullptr, nullptr };
            fused_reduce_ln<<<dim3(MM, 1), 256>>>(rp);
            const int ffm[1] = { 5 };
            const int ffslots[1] = { 0 };
            run_ff_gemms(1, ffm, ffslots);
            FRdBatch rb = {};
            // O: ln2(next) -> slot6
            rb.s[0] = { part, ff_b2 + 5*DD, O, O, 4, 1,
                        ln_g + 2*DD, ln_b + 2*DD, LS(6), LSl(6),
                        nullptr, nullptr, nullptr, nullptr };
            fused_reduce_ln<<<dim3(MM, 1), 256>>>(rb);
        }
    }
}

// round 13
// speedup vs baseline: 1.8249x; 1.6421x over previous
#include <cuda_runtime.h>
#include <cuda_bf16.h>
#include <stdint.h>
#include <math.h>

#define BB 2
#define SS 1024
#define DD 256
#define HH 4
#define CC 64
#define WINSZ 10
#define NITER 2
#define MM 2048
#define HID 2048
#define BSD (BB*SS*DD)
#define MH ((size_t)MM*HID)
#define MD ((size_t)MM*DD)

typedef __nv_bfloat16 bf16;

// ---------------- scratch (device globals; no allocation) -------------------
__device__ float g_Q[3*BSD], g_Kb[3*BSD], g_Vb[3*BSD], g_Gb[3*BSD];
__device__ float g_b56[DD];
__device__ float g_part[12*MD];
__device__ bf16 g_lnh[7*BSD], g_lnl[7*BSD];
__device__ bf16 g_cth[3*BSD], g_ctl[3*BSD];
__device__ bf16 g_hidh[3*MH], g_hidl[3*MH];

__device__ bf16 g_WqTh[7*DD*DD], g_WqTl[7*DD*DD];
__device__ bf16 g_WkTh[7*DD*DD], g_WkTl[7*DD*DD];
__device__ bf16 g_WvTh[7*DD*DD], g_WvTl[7*DD*DD];
__device__ bf16 g_GwTh[7*DD*DD], g_GwTl[7*DD*DD];
__device__ bf16 g_OwTh[7*DD*DD], g_OwTl[7*DD*DD];
__device__ bf16 g_w1Th[(size_t)6*DD*HID], g_w1Tl[(size_t)6*DD*HID];
__device__ bf16 g_w2Th[(size_t)6*HID*DD], g_w2Tl[(size_t)6*HID*DD];

__device__ __forceinline__ void split2(float v, bf16& h, bf16& l){
    h = __float2bfloat16(v);
    l = __float2bfloat16(v - __bfloat162float(h));
}
__device__ __forceinline__ uint32_t smem_u32(const void* p){
    uint32_t a;
    asm("{ .reg .u64 t; cvta.to.shared.u64 t, %1; cvt.u32.u64 %0, t; }" : "=r"(a) : "l"(p));
    return a;
}
__device__ __forceinline__ void cp16(uint32_t saddr, const void* g){
    asm volatile("cp.async.cg.shared.global [%0], [%1], 16;" :: "r"(saddr), "l"(g));
}
__device__ __forceinline__ void ldsm_x4(uint32_t* r, uint32_t addr){
    asm volatile("ldmatrix.sync.aligned.m8n8.x4.shared.b16 {%0,%1,%2,%3}, [%4];"
        : "=r"(r[0]), "=r"(r[1]), "=r"(r[2]), "=r"(r[3]) : "r"(addr));
}
__device__ __forceinline__ float warp_sum(float s){
    #pragma unroll
    for (int o = 16; o > 0; o >>= 1) s += __shfl_xor_sync(0xffffffffu, s, o);
    return s;
}
// pack 8 floats -> hi/lo bf16 uint4 pair and store
__device__ __forceinline__ void store8(bf16* oh, bf16* ol, size_t base, const float* v){
    __align__(16) bf16 h[8], l[8];
    #pragma unroll
    for (int i = 0; i < 8; i++) split2(v[i], h[i], l[i]);
    *(uint4*)&oh[base] = *(const uint4*)h;
    *(uint4*)&ol[base] = *(const uint4*)l;
}

// ---------------- weight transpose + split ----------------------------------
__device__ __forceinline__ void wsplit_body(
    const float* w, bf16* th, bf16* tl, int N, int ldt)
{
    __shared__ float sm[32][33];
    int n0 = blockIdx.x * 32, k0 = blockIdx.y * 32;
    int tx = threadIdx.x & 31, ty = threadIdx.x >> 5;
    #pragma unroll
    for (int i = 0; i < 4; i++)
        sm[ty + i*8][tx] = w[(size_t)(k0 + ty + i*8) * N + n0 + tx];
    __syncthreads();
    #pragma unroll
    for (int i = 0; i < 4; i++) {
        int n = n0 + ty + i*8;
        bf16 h, l; split2(sm[tx][ty + i*8], h, l);
        th[(size_t)n * ldt + k0 + tx] = h;
        tl[(size_t)n * ldt + k0 + tx] = l;
    }
}

struct WsAll { const float* src[5]; bf16* th[5]; bf16* tl[5]; const float* aOb; };
__global__ void __launch_bounds__(256) wsplit_all(WsAll wa)
{
    if (blockIdx.z == 35) {
        if (blockIdx.x == 0 && blockIdx.y == 0 && threadIdx.x < DD)
            g_b56[threadIdx.x] = wa.aOb[5*DD + threadIdx.x] + wa.aOb[6*DD + threadIdx.x];
        return;
    }
    int fam = blockIdx.z / 7, mod = blockIdx.z % 7;
    wsplit_body(wa.src[fam] + (size_t)mod*DD*DD,
                wa.th[fam] + (size_t)mod*DD*DD, wa.tl[fam] + (size_t)mod*DD*DD,
                DD, DD);
}
__global__ void __launch_bounds__(256) wsplit_big(
    const float* __restrict__ W, bf16* __restrict__ Th, bf16* __restrict__ Tl,
    int K, int N, long long wstride, long long tstride)
{
    wsplit_body(W + (size_t)blockIdx.z * wstride,
                Th + (size_t)blockIdx.z * tstride, Tl + (size_t)blockIdx.z * tstride,
                N, K);
}

// ---------------- warp-per-row LayerNorm (batched over z) -------------------
struct LnS { const float* x; const float* g; const float* b; bf16* oh; bf16* ol; };
struct LnBatch { LnS s[3]; };

__global__ void __launch_bounds__(256) ln_kernel(LnBatch lb)
{
    LnS sl = lb.s[blockIdx.y];
    int wid = threadIdx.x >> 5, lane = threadIdx.x & 31;
    int row = blockIdx.x * 8 + wid;
    size_t base = (size_t)row * DD + lane * 8;

    float v[8];
    float4 p0 = *(const float4*)&sl.x[base];
    float4 p1 = *(const float4*)&sl.x[base + 4];
    v[0]=p0.x; v[1]=p0.y; v[2]=p0.z; v[3]=p0.w;
    v[4]=p1.x; v[5]=p1.y; v[6]=p1.z; v[7]=p1.w;

    float s = 0.f;
    #pragma unroll
    for (int i = 0; i < 8; i++) s += v[i];
    float mean = warp_sum(s) * (1.0f/DD);
    float q = 0.f;
    #pragma unroll
    for (int i = 0; i < 8; i++) { float d = v[i]-mean; q += d*d; }
    float rstd = rsqrtf(warp_sum(q) * (1.0f/DD) + 1e-5f);

    int c = lane * 8;
    float4 g0 = *(const float4*)&sl.g[c], g1 = *(const float4*)&sl.g[c+4];
    float4 b0 = *(const float4*)&sl.b[c], b1 = *(const float4*)&sl.b[c+4];
    float gg[8] = {g0.x,g0.y,g0.z,g0.w,g1.x,g1.y,g1.z,g1.w};
    float bb[8] = {b0.x,b0.y,b0.z,b0.w,b1.x,b1.y,b1.z,b1.w};
    float out[8];
    #pragma unroll
    for (int i = 0; i < 8; i++) out[i] = (v[i]-mean)*rstd*gg[i] + bb[i];
    store8(sl.oh, sl.ol, base, out);
}

// ---------------- fused split-K reduce + LN(s), warp-per-row ----------------
struct FRdS {
    const float* p; const float* bias; const float* res; float* dst; int nsplit;
    int nln;
    const float *lg0, *lb0; bf16 *oh0, *ol0;
    const float *lg1, *lb1; bf16 *oh1, *ol1;
};
struct FRdBatch { FRdS s[3]; };

__global__ void __launch_bounds__(256) fused_reduce_ln(FRdBatch rb)
{
    FRdS sl = rb.s[blockIdx.y];
    int wid = threadIdx.x >> 5, lane = threadIdx.x & 31;
    int row = blockIdx.x * 8 + wid;
    size_t base = (size_t)row * DD + lane * 8;
    int c = lane * 8;

    float a[8];
    {
        float4 p0 = *(const float4*)&sl.p[base];
        float4 p1 = *(const float4*)&sl.p[base + 4];
        a[0]=p0.x; a[1]=p0.y; a[2]=p0.z; a[3]=p0.w;
        a[4]=p1.x; a[5]=p1.y; a[6]=p1.z; a[7]=p1.w;
    }
    for (int s = 1; s < sl.nsplit; s++) {
        float4 p0 = *(const float4*)&sl.p[(size_t)s*MD + base];
        float4 p1 = *(const float4*)&sl.p[(size_t)s*MD + base + 4];
        a[0]+=p0.x; a[1]+=p0.y; a[2]+=p0.z; a[3]+=p0.w;
        a[4]+=p1.x; a[5]+=p1.y; a[6]+=p1.z; a[7]+=p1.w;
    }
    {
        float4 b0 = *(const float4*)&sl.bias[c], b1 = *(const float4*)&sl.bias[c+4];
        a[0]+=b0.x; a[1]+=b0.y; a[2]+=b0.z; a[3]+=b0.w;
        a[4]+=b1.x; a[5]+=b1.y; a[6]+=b1.z; a[7]+=b1.w;
    }
    if (sl.res) {
        float4 r0 = *(const float4*)&sl.res[base], r1 = *(const float4*)&sl.res[base+4];
        a[0]+=r0.x; a[1]+=r0.y; a[2]+=r0.z; a[3]+=r0.w;
        a[4]+=r1.x; a[5]+=r1.y; a[6]+=r1.z; a[7]+=r1.w;
    }
    {
        float4 o0 = make_float4(a[0],a[1],a[2],a[3]);
        float4 o1 = make_float4(a[4],a[5],a[6],a[7]);
        *(float4*)&sl.dst[base] = o0;
        *(float4*)&sl.dst[base+4] = o1;
    }

    float s = 0.f;
    #pragma unroll
    for (int i = 0; i < 8; i++) s += a[i];
    float mean = warp_sum(s) * (1.0f/DD);
    float q = 0.f;
    #pragma unroll
    for (int i = 0; i < 8; i++) { float d = a[i]-mean; q += d*d; }
    float rstd = rsqrtf(warp_sum(q) * (1.0f/DD) + 1e-5f);

    float nrm[8];
    #pragma unroll
    for (int i = 0; i < 8; i++) nrm[i] = (a[i]-mean)*rstd;

    {
        float4 g0 = *(const float4*)&sl.lg0[c], g1 = *(const float4*)&sl.lg0[c+4];
        float4 b0 = *(const float4*)&sl.lb0[c], b1 = *(const float4*)&sl.lb0[c+4];
        float gg[8] = {g0.x,g0.y,g0.z,g0.w,g1.x,g1.y,g1.z,g1.w};
        float bb[8] = {b0.x,b0.y,b0.z,b0.w,b1.x,b1.y,b1.z,b1.w};
        float out[8];
        #pragma unroll
        for (int i = 0; i < 8; i++) out[i] = nrm[i]*gg[i] + bb[i];
        store8(sl.oh0, sl.ol0, base, out);
    }
    if (sl.nln > 1) {
        float4 g0 = *(const float4*)&sl.lg1[c], g1 = *(const float4*)&sl.lg1[c+4];
        float4 b0 = *(const float4*)&sl.lb1[c], b1 = *(const float4*)&sl.lb1[c+4];
        float gg[8] = {g0.x,g0.y,g0.z,g0.w,g1.x,g1.y,g1.z,g1.w};
        float bb[8] = {b0.x,b0.y,b0.z,b0.w,b1.x,b1.y,b1.z,b1.w};
        float out[8];
        #pragma unroll
        for (int i = 0; i < 8; i++) out[i] = nrm[i]*gg[i] + bb[i];
        store8(sl.oh1, sl.ol1, base, out);
    }
}

// ---------------- batched split-compensated MMA GEMM ------------------------
struct Slice {
    const bf16 *Ah, *Al, *Bh, *Bl;
    const float *bias, *res;
    float* C; bf16 *Ch, *Cl;
    int mode, lda, ldb, Ksub;
};
struct Batch { Slice s[12]; };

#define BKC 32
#define LDSB 40
#define ARRE (128*LDSB)
#define STGE (4*ARRE)
#define GSMEM (2*STGE*2)

__device__ __forceinline__ void mma16816(float* c, const uint32_t* a, const uint32_t* b){
    asm volatile("mma.sync.aligned.m16n8k16.row.col.f32.bf16.bf16.f32 "
        "{%0,%1,%2,%3}, {%4,%5,%6,%7}, {%8,%9}, {%0,%1,%2,%3};"
        : "+f"(c[0]), "+f"(c[1]), "+f"(c[2]), "+f"(c[3])
        : "r"(a[0]), "r"(a[1]), "r"(a[2]), "r"(a[3]), "r"(b[0]), "r"(b[1]));
}

__global__ void __launch_bounds__(256,2)
gemm_batched(Batch bt, int M, int N)
{
    extern __shared__ __align__(16) bf16 smem[];
    const Slice sl = bt.s[blockIdx.z];
    const int tid  = threadIdx.x;
    const int warp = tid >> 5, lane = tid & 31;
    const int wm = warp >> 2, wn = warp & 3;
    const int row0 = blockIdx.y * 128, col0 = blockIdx.x * 128;
    const int g8 = lane >> 2, tig = lane & 3;
    const uint32_t sb = smem_u32(smem);
    const int NC = sl.Ksub / BKC;
    const int lda = sl.lda, ldb = sl.ldb;

    float acc[4][4][4];
    #pragma unroll
    for (int i=0;i<4;i++) for (int j=0;j<4;j++) for (int q=0;q<4;q++) acc[i][j][q]=0.f;

    const int ck0 = tid, ck1 = tid + 256;
    const int r0c = ck0 >> 2, c0c = (ck0 & 3) * 8;
    const int r1c = ck1 >> 2, c1c = (ck1 & 3) * 8;

    const int lmat = lane >> 3, lrow = lane & 7;
    const uint32_t a_lane_off = (uint32_t)(((lmat & 1) * 8 + lrow) * LDSB + (lmat >> 1) * 8) * 2;
    const uint32_t b_lane_off = (uint32_t)(((lmat >> 1) * 8 + lrow) * LDSB + (lmat & 1) * 8) * 2;

    auto cpStage = [&](int c, int st){
        int kc = c * BKC;
        uint32_t base = sb + (uint32_t)(st * STGE) * 2;
        uint32_t so0 = (uint32_t)(r0c * LDSB + c0c) * 2;
        uint32_t so1 = (uint32_t)(r1c * LDSB + c1c) * 2;
        cp16(base + so0,            sl.Ah + (size_t)(row0 + r0c) * lda + kc + c0c);
        cp16(base + so1,            sl.Ah + (size_t)(row0 + r1c) * lda + kc + c1c);
        cp16(base + ARRE*2 + so0,   sl.Al + (size_t)(row0 + r0c) * lda + kc + c0c);
        cp16(base + ARRE*2 + so1,   sl.Al + (size_t)(row0 + r1c) * lda + kc + c1c);
        cp16(base + ARRE*4 + so0,   sl.Bh + (size_t)(col0 + r0c) * ldb + kc + c0c);
        cp16(base + ARRE*4 + so1,   sl.Bh + (size_t)(col0 + r1c) * ldb + kc + c1c);
        cp16(base + ARRE*6 + so0,   sl.Bl + (size_t)(col0 + r0c) * ldb + kc + c0c);
        cp16(base + ARRE*6 + so1,   sl.Bl + (size_t)(col0 + r1c) * ldb + kc + c1c);
        asm volatile("cp.async.commit_group;" ::: "memory");
    };

    cpStage(0, 0);
    if (NC > 1) cpStage(1, 1);
    else asm volatile("cp.async.commit_group;" ::: "memory");

    for (int c = 0; c < NC; c++) {
        const int st = c & 1;
        if (c + 2 < NC) asm volatile("cp.async.wait_group 1;" ::: "memory");
        else            asm volatile("cp.async.wait_group 0;" ::: "memory");
        __syncthreads();

        const uint32_t sA_h = sb + (uint32_t)(st*STGE) * 2;
        const uint32_t sA_l = sA_h + ARRE*2;
        const uint32_t sB_h = sA_h + ARRE*4;
        const uint32_t sB_l = sA_h + ARRE*6;

        #pragma unroll
        for (int kk = 0; kk < 2; kk++) {
            const uint32_t kbo = (uint32_t)(kk * 16) * 2;
            uint32_t bh[4][2], bl[4][2];
            #pragma unroll
            for (int pr = 0; pr < 2; pr++) {
                uint32_t nbase = (uint32_t)((wn*32 + pr*16) * LDSB) * 2;
                uint32_t r4[4];
                ldsm_x4(r4, sB_h + nbase + kbo + b_lane_off);
                bh[pr*2][0] = r4[0]; bh[pr*2][1] = r4[1];
                bh[pr*2+1][0] = r4[2]; bh[pr*2+1][1] = r4[3];
                ldsm_x4(r4, sB_l + nbase + kbo + b_lane_off);
                bl[pr*2][0] = r4[0]; bl[pr*2][1] = r4[1];
                bl[pr*2+1][0] = r4[2]; bl[pr*2+1][1] = r4[3];
            }
            #pragma unroll
            for (int mi = 0; mi < 4; mi++) {
                uint32_t rbase = (uint32_t)((wm*64 + mi*16) * LDSB) * 2;
                uint32_t ah[4], al[4];
                ldsm_x4(ah, sA_h + rbase + kbo + a_lane_off);
                ldsm_x4(al, sA_l + rbase + kbo + a_lane_off);
                #pragma unroll
                for (int ni = 0; ni < 4; ni++) {
                    mma16816(acc[mi][ni], ah, bh[ni]);
                    mma16816(acc[mi][ni], ah, bl[ni]);
                    mma16816(acc[mi][ni], al, bh[ni]);
                }
            }
        }
        __syncthreads();
        if (c + 2 < NC) cpStage(c + 2, st);
    }

    #pragma unroll
    for (int mi = 0; mi < 4; mi++) {
        #pragma unroll
        for (int ni = 0; ni < 4; ni++) {
            int r1 = row0 + wm*64 + mi*16 + g8;
            int c1 = col0 + wn*32 + ni*8 + tig*2;
            #pragma unroll
            for (int q = 0; q < 4; q++) {
                int r = (q < 2) ? r1 : r1 + 8;
                int cc = c1 + (q & 1);
                float v = acc[mi][ni][q];
                if (sl.bias) v += sl.bias[cc];
                if (sl.mode == 1)      v = fmaxf(v, 0.f);
                else if (sl.mode == 2) v = 1.f / (1.f + __expf(-v));
                if (sl.Ch) {
                    bf16 h, l; split2(v, h, l);
                    sl.Ch[(size_t)r * N + cc] = h;
                    sl.Cl[(size_t)r * N + cc] = l;
                } else {
                    if (sl.res) v += sl.res[(size_t)r * N + cc];
                    sl.C[(size_t)r * N + cc] = v;
                }
            }
        }
    }
}

// ---------------- windowed attention core (batched over z) ------------------
struct AtS { const float* Q; const float* K; const float* V; const float* G;
             bf16* cth; bf16* ctl; };
struct AtBatch { AtS s[3]; };

__global__ void __launch_bounds__(256)
attn_core_kernel(AtBatch ab, const unsigned char* __restrict__ mask)
{
    AtS sl = ab.s[blockIdx.y];
    int idx  = blockIdx.x * blockDim.x + threadIdx.x;
    int gw   = idx >> 5;
    int lane = idx & 31;
    int s = gw & (SS - 1);
    int h = (gw >> 10) & (HH - 1);
    int n = gw >> 12;

    int base_q = (n * SS + s) * DD + h * CC;
    float q0 = sl.Q[base_q + lane];
    float q1 = sl.Q[base_q + 32 + lane];

    int t0 = s - WINSZ; if (t0 < 0) t0 = 0;
    int t1 = s + WINSZ; if (t1 > SS - 1) t1 = SS - 1;
    int cnt = t1 - t0 + 1;

    float sc[2 * WINSZ + 1];
    float mx = -1e30f;
    for (int i = 0; i < cnt; i++) {
        int t = t0 + i;
        float v;
        if (mask[n * SS + t]) v = -1e30f;
        else {
            int bk = (n * SS + t) * DD + h * CC;
            float p = q0 * sl.K[bk + lane] + q1 * sl.K[bk + 32 + lane];
            #pragma unroll
            for (int o = 16; o > 0; o >>= 1) p += __shfl_xor_sync(0xffffffffu, p, o);
            v = p * 0.125f;
        }
        sc[i] = v;
        mx = fmaxf(mx, v);
    }
    float denom = 0.f;
    for (int i = 0; i < cnt; i++) {
        float e = (sc[i] <= -1e29f) ? 0.f : __expf(sc[i] - mx);
        sc[i] = e; denom += e;
    }
    float inv = (denom > 0.f) ? (1.f / denom) : 0.f;
    float o0 = 0.f, o1 = 0.f;
    for (int i = 0; i < cnt; i++) {
        int bv = (n * SS + (t0 + i)) * DD + h * CC;
        float a = sc[i] * inv;
        o0 = fmaf(a, sl.V[bv + lane], o0);
        o1 = fmaf(a, sl.V[bv + 32 + lane], o1);
    }
    float v0 = o0 * sl.G[base_q + lane];
    float v1 = o1 * sl.G[base_q + 32 + lane];
    bf16 h0, l0, h1, l1;
    split2(v0, h0, l0); split2(v1, h1, l1);
    sl.cth[base_q + lane]      = h0;  sl.ctl[base_q + lane]      = l0;
    sl.cth[base_q + 32 + lane] = h1;  sl.ctl[base_q + 32 + lane] = l1;
}

// ---------------- host orchestration ----------------------------------------
extern "C" void kernel_launch(void* const* d_in, const int* in_sizes, int n_in,
                              void* d_out, int out_size)
{
    (void)in_sizes; (void)n_in; (void)out_size;
    const float* inL = (const float*)d_in[0];
    const float* inN = (const float*)d_in[1];
    const float* inO = (const float*)d_in[2];
    const unsigned char* mask = (const unsigned char*)d_in[3];
    const float* aWq = (const float*)d_in[4];
    const float* aWk = (const float*)d_in[5];
    const float* aWv = (const float*)d_in[6];
    const float* aGw = (const float*)d_in[7];
    const float* aGb = (const float*)d_in[8];
    const float* aOw = (const float*)d_in[9];
    const float* aOb = (const float*)d_in[10];
    const float* ln_g = (const float*)d_in[11];
    const float* ln_b = (const float*)d_in[12];
    const float* ff_g = (const float*)d_in[13];
    const float* ff_b = (const float*)d_in[14];
    const float* ff_w1 = (const float*)d_in[15];
    const float* ff_b1 = (const float*)d_in[16];
    const float* ff_w2 = (const float*)d_in[17];
    const float* ff_b2 = (const float*)d_in[18];

    float* L  = (float*)d_out;
    float* Nb = L + BSD;
    float* O  = Nb + BSD;
    float* X[3] = { L, Nb, O };

    cudaMemcpyAsync(L,  inL, (size_t)BSD * sizeof(float), cudaMemcpyDeviceToDevice);
    cudaMemcpyAsync(Nb, inN, (size_t)BSD * sizeof(float), cudaMemcpyDeviceToDevice);
    cudaMemcpyAsync(O,  inO, (size_t)BSD * sizeof(float), cudaMemcpyDeviceToDevice);

    void* pa;
    #define SYM(var, sym) cudaGetSymbolAddress(&pa, sym); auto var = (decltype(&sym[0]))pa;
    SYM(Qb, g_Q) SYM(Kb, g_Kb) SYM(Vb, g_Vb) SYM(Gg, g_Gb)
    SYM(lnh, g_lnh) SYM(lnl, g_lnl)
    SYM(cth, g_cth) SYM(ctl, g_ctl)
    SYM(hidh, g_hidh) SYM(hidl, g_hidl)
    SYM(b56, g_b56) SYM(part, g_part)
    SYM(wqh, g_WqTh) SYM(wql, g_WqTl) SYM(wkh, g_WkTh) SYM(wkl, g_WkTl)
    SYM(wvh, g_WvTh) SYM(wvl, g_WvTl) SYM(gwh, g_GwTh) SYM(gwl, g_GwTl)
    SYM(owh, g_OwTh) SYM(owl, g_OwTl)
    SYM(w1h, g_w1Th) SYM(w1l, g_w1Tl) SYM(w2h, g_w2Th) SYM(w2l, g_w2Tl)
    #undef SYM

    cudaFuncSetAttribute(gemm_batched, cudaFuncAttributeMaxDynamicSharedMemorySize, GSMEM);

    // ---- weight prep: 3 launches ----
    {
        WsAll wa;
        wa.src[0]=aWq; wa.src[1]=aWk; wa.src[2]=aWv; wa.src[3]=aGw; wa.src[4]=aOw;
        wa.th[0]=wqh; wa.th[1]=wkh; wa.th[2]=wvh; wa.th[3]=gwh; wa.th[4]=owh;
        wa.tl[0]=wql; wa.tl[1]=wkl; wa.tl[2]=wvl; wa.tl[3]=gwl; wa.tl[4]=owl;
        wa.aOb = aOb;
        wsplit_all<<<dim3(8, 8, 36), 256>>>(wa);
        wsplit_big<<<dim3(HID/32, DD/32, 6), 256>>>(ff_w1, w1h, w1l, DD, HID,
                                                    (long long)DD*HID, (long long)DD*HID);
        wsplit_big<<<dim3(DD/32, HID/32, 6), 256>>>(ff_w2, w2h, w2l, HID, DD,
                                                    (long long)HID*DD, (long long)HID*DD);
    }

    float* QKVG[4] = { Qb, Kb, Vb, Gg };
    auto LS = [&](int slot) { return lnh + (size_t)slot*BSD; };
    auto LSl = [&](int slot) { return lnl + (size_t)slot*BSD; };

    auto run_ln = [&](int nz, const float* xs[], const float* gbase, const float* bbase,
                      const int* ks, const int* slots) {
        LnBatch lb;
        for (int j = 0; j < nz; j++)
            lb.s[j] = { xs[j], gbase + (size_t)ks[j]*DD, bbase + (size_t)ks[j]*DD,
                        LS(slots[j]), LSl(slots[j]) };
        ln_kernel<<<dim3(MM/8, nz), 256>>>(lb);
    };

    auto run_qkvg = [&](int nz, const int* mods, const int* qslot, const int* kvslot) {
        Batch bt = {};
        for (int j = 0; j < nz; j++) {
            int k = mods[j];
            for (int c = 0; c < 4; c++) {
                Slice& s = bt.s[j*4 + c];
                int slot = (c == 0) ? qslot[j] : kvslot[j];
                s.Ah = LS(slot); s.Al = LSl(slot);
                const bf16* bh[4] = { wqh, wkh, wvh, gwh };
                const bf16* bl[4] = { wql, wkl, wvl, gwl };
                s.Bh = bh[c] + (size_t)k*DD*DD;
                s.Bl = bl[c] + (size_t)k*DD*DD;
                s.bias = (c == 3) ? (aGb + (size_t)k*DD) : nullptr;
                s.C = QKVG[c] + (size_t)j*BSD;
                s.mode = (c == 3) ? 2 : 0;
                s.lda = DD; s.ldb = DD; s.Ksub = DD;
            }
        }
        gemm_batched<<<dim3(DD/128, MM/128, nz*4), 256, GSMEM>>>(bt, MM, DD);
    };

    auto run_attn = [&](int nz) {
        AtBatch ab = {};
        for (int j = 0; j < nz; j++)
            ab.s[j] = { Qb + (size_t)j*BSD, Kb + (size_t)j*BSD, Vb + (size_t)j*BSD,
                        Gg + (size_t)j*BSD, cth + (size_t)j*BSD, ctl + (size_t)j*BSD };
        attn_core_kernel<<<dim3((BB*HH*SS*32)/256, nz), 256>>>(ab, mask);
    };

    auto run_proj = [&](int nz, const int* mods, float* const* dst) {
        Batch bt = {};
        for (int j = 0; j < nz; j++) {
            int k = mods[j];
            Slice& s = bt.s[j];
            s.Ah = cth + (size_t)j*BSD;
            s.Al = ctl + (size_t)j*BSD;
            s.Bh = owh + (size_t)k*DD*DD;
            s.Bl = owl + (size_t)k*DD*DD;
            s.bias = aOb + (size_t)k*DD;
            s.res = dst[j]; s.C = dst[j];
            s.lda = DD; s.ldb = DD; s.Ksub = DD;
        }
        gemm_batched<<<dim3(DD/128, MM/128, nz), 256, GSMEM>>>(bt, MM, DD);
    };

    auto run_ff_gemms = [&](int nz, const int* mods, const int* lnslots) {
        Batch b1 = {};
        for (int j = 0; j < nz; j++) {
            Slice& s = b1.s[j];
            s.Ah = LS(lnslots[j]); s.Al = LSl(lnslots[j]);
            s.Bh = w1h + (size_t)mods[j]*DD*HID; s.Bl = w1l + (size_t)mods[j]*DD*HID;
            s.bias = ff_b1 + (size_t)mods[j]*HID;
            s.Ch = hidh + (size_t)j*MH; s.Cl = hidl + (size_t)j*MH;
            s.mode = 1; s.lda = DD; s.ldb = DD; s.Ksub = DD;
        }
        gemm_batched<<<dim3(HID/128, MM/128, nz), 256, GSMEM>>>(b1, MM, HID);
        Batch b2 = {};
        for (int j = 0; j < nz; j++)
            for (int sp = 0; sp < 4; sp++) {
                Slice& s = b2.s[j*4 + sp];
                s.Ah = hidh + (size_t)j*MH + sp*512;
                s.Al = hidl + (size_t)j*MH + sp*512;
                s.Bh = w2h + (size_t)mods[j]*HID*DD + sp*512;
                s.Bl = w2l + (size_t)mods[j]*HID*DD + sp*512;
                s.C = part + (size_t)(j*4 + sp)*MD;
                s.lda = HID; s.ldb = HID; s.Ksub = 512;
            }
        gemm_batched<<<dim3(DD/128, MM/128, nz*4), 256, GSMEM>>>(b2, MM, DD);
    };

    // initial block-LNs: ln0->4, ln1->5, ln2->6
    {
        const float* xs[3] = { L, Nb, O };
        const int lnk[3] = { 0, 1, 2 };
        const int slots[3] = { 4, 5, 6 };
        run_ln(3, xs, ln_g, ln_b, lnk, slots);
    }

    for (int it = 0; it < NITER; it++) {
        // -------- Phase 1: self blocks --------
        {
            const int mods[3] = { 0, 1, 2 };
            const int slots[3] = { 4, 5, 6 };
            run_qkvg(3, mods, slots, slots);
            run_attn(3);
            run_proj(3, mods, X);
            const float* xs[3] = { L, Nb, O };
            const int ffslots[3] = { 0, 1, 2 };
            run_ln(3, xs, ff_g, ff_b, mods, ffslots);
            run_ff_gemms(3, mods, ffslots);
            FRdBatch rb = {};
            rb.s[0] = { part + 0*4*MD, ff_b2 + 0*DD, L, L, 4, 1,
                        ln_g + 4*DD, ln_b + 4*DD, LS(0), LSl(0),
                        nullptr, nullptr, nullptr, nullptr };
            rb.s[1] = { part + 1*4*MD, ff_b2 + 1*DD, Nb, Nb, 4, 1,
                        ln_g + 5*DD, ln_b + 5*DD, LS(1), LSl(1),
                        nullptr, nullptr, nullptr, nullptr };
            rb.s[2] = { part + 2*4*MD, ff_b2 + 2*DD, O, O, 4, 2,
                        ln_g + 3*DD, ln_b + 3*DD, LS(3), LSl(3),
                        ln_g + 8*DD, ln_b + 8*DD, LS(2), LSl(2) };
            fused_reduce_ln<<<dim3(MM/8, 3), 256>>>(rb);
        }
        // -------- Phase 2: cross blocks --------
        {
            const int mods[2] = { 3, 4 };
            const int qslot[2] = { 0, 1 };
            const int kvslot[2] = { 3, 3 };
            run_qkvg(2, mods, qslot, kvslot);
            run_attn(2);
            float* dst[2] = { L, Nb };
            run_proj(2, mods, dst);
            const float* xs[2] = { L, Nb };
            const int ffslots[2] = { 0, 1 };
            run_ln(2, xs, ff_g, ff_b, mods, ffslots);
            run_ff_gemms(2, mods, ffslots);
            FRdBatch rb = {};
            rb.s[0] = { part + 0*4*MD, ff_b2 + 3*DD, L, L, 4, 2,
                        ln_g + 6*DD, ln_b + 6*DD, LS(0), LSl(0),
                        ln_g + 0*DD, ln_b + 0*DD, LS(4), LSl(4) };
            rb.s[1] = { part + 1*4*MD, ff_b2 + 4*DD, Nb, Nb, 4, 2,
                        ln_g + 7*DD, ln_b + 7*DD, LS(1), LSl(1),
                        ln_g + 1*DD, ln_b + 1*DD, LS(5), LSl(5) };
            fused_reduce_ln<<<dim3(MM/8, 2), 256>>>(rb);
        }
        // -------- Phase 3: O update --------
        {
            const int mods[2] = { 5, 6 };
            const int qslot[2] = { 2, 2 };
            const int kvslot[2] = { 1, 0 };
            run_qkvg(2, mods, qslot, kvslot);
            run_attn(2);
            Batch bp = {};
            for (int sp = 0; sp < 2; sp++) {
                Slice& s = bp.s[sp];
                s.Ah = cth + (size_t)sp*BSD;
                s.Al = ctl + (size_t)sp*BSD;
                s.Bh = owh + (size_t)(5 + sp)*DD*DD;
                s.Bl = owl + (size_t)(5 + sp)*DD*DD;
                s.C = part + (size_t)sp*MD;
                s.lda = DD; s.ldb = DD; s.Ksub = DD;
            }
            gemm_batched<<<dim3(DD/128, MM/128, 2), 256, GSMEM>>>(bp, MM, DD);
            FRdBatch rp = {};
            rp.s[0] = { part, b56, O, O, 2, 1,
                        ff_g + 5*DD, ff_b + 5*DD, LS(0), LSl(0),
                        nullptr, nullptr, nullptr, nullptr };
            fused_reduce_ln<<<dim3(MM/8, 1), 256>>>(rp);
            const int ffm[1] = { 5 };
            const int ffslots[1] = { 0 };
            run_ff_gemms(1, ffm, ffslots);
            FRdBatch rb = {};
            rb.s[0] = { part, ff_b2 + 5*DD, O, O, 4, 1,
                        ln_g + 2*DD, ln_b + 2*DD, LS(6), LSl(6),
                        nullptr, nullptr, nullptr, nullptr };
            fused_reduce_ln<<<dim3(MM/8, 1), 256>>>(rb);
        }
    }
}

// round 14
// speedup vs baseline: 1.9204x; 1.0523x over previous
#include <cuda_runtime.h>
#include <cuda_bf16.h>
#include <stdint.h>
#include <math.h>

#define BB 2
#define SS 1024
#define DD 256
#define HH 4
#define CC 64
#define WINSZ 10
#define NITER 2
#define MM 2048
#define HID 2048
#define BSD (BB*SS*DD)
#define MH ((size_t)MM*HID)
#define MD ((size_t)MM*DD)

typedef __nv_bfloat16 bf16;

// ---------------- scratch (device globals; no allocation) -------------------
__device__ float g_Q[3*BSD], g_Kb[3*BSD], g_Vb[3*BSD], g_Gb[3*BSD];
__device__ float g_b56[DD];
__device__ float g_part[12*MD];
__device__ bf16 g_lnh[7*BSD], g_lnl[7*BSD];
__device__ bf16 g_cth[3*BSD], g_ctl[3*BSD];
__device__ bf16 g_hidh[3*MH], g_hidl[3*MH];

__device__ bf16 g_WqTh[7*DD*DD], g_WqTl[7*DD*DD];
__device__ bf16 g_WkTh[7*DD*DD], g_WkTl[7*DD*DD];
__device__ bf16 g_WvTh[7*DD*DD], g_WvTl[7*DD*DD];
__device__ bf16 g_GwTh[7*DD*DD], g_GwTl[7*DD*DD];
__device__ bf16 g_OwTh[7*DD*DD], g_OwTl[7*DD*DD];
__device__ bf16 g_w1Th[(size_t)6*DD*HID], g_w1Tl[(size_t)6*DD*HID];
__device__ bf16 g_w2Th[(size_t)6*HID*DD], g_w2Tl[(size_t)6*HID*DD];

__device__ __forceinline__ void split2(float v, bf16& h, bf16& l){
    h = __float2bfloat16(v);
    l = __float2bfloat16(v - __bfloat162float(h));
}
__device__ __forceinline__ uint32_t smem_u32(const void* p){
    uint32_t a;
    asm("{ .reg .u64 t; cvta.to.shared.u64 t, %1; cvt.u32.u64 %0, t; }" : "=r"(a) : "l"(p));
    return a;
}
__device__ __forceinline__ void cp16(uint32_t saddr, const void* g){
    asm volatile("cp.async.cg.shared.global [%0], [%1], 16;" :: "r"(saddr), "l"(g));
}
__device__ __forceinline__ void ldsm_x4(uint32_t* r, uint32_t addr){
    asm volatile("ldmatrix.sync.aligned.m8n8.x4.shared.b16 {%0,%1,%2,%3}, [%4];"
        : "=r"(r[0]), "=r"(r[1]), "=r"(r[2]), "=r"(r[3]) : "r"(addr));
}
__device__ __forceinline__ float warp_sum(float s){
    #pragma unroll
    for (int o = 16; o > 0; o >>= 1) s += __shfl_xor_sync(0xffffffffu, s, o);
    return s;
}
__device__ __forceinline__ void store8(bf16* oh, bf16* ol, size_t base, const float* v){
    __align__(16) bf16 h[8], l[8];
    #pragma unroll
    for (int i = 0; i < 8; i++) split2(v[i], h[i], l[i]);
    *(uint4*)&oh[base] = *(const uint4*)h;
    *(uint4*)&ol[base] = *(const uint4*)l;
}

// ---------------- weight transpose + split ----------------------------------
__device__ __forceinline__ void wsplit_body(
    const float* w, bf16* th, bf16* tl, int N, int ldt)
{
    __shared__ float sm[32][33];
    int n0 = blockIdx.x * 32, k0 = blockIdx.y * 32;
    int tx = threadIdx.x & 31, ty = threadIdx.x >> 5;
    #pragma unroll
    for (int i = 0; i < 4; i++)
        sm[ty + i*8][tx] = w[(size_t)(k0 + ty + i*8) * N + n0 + tx];
    __syncthreads();
    #pragma unroll
    for (int i = 0; i < 4; i++) {
        int n = n0 + ty + i*8;
        bf16 h, l; split2(sm[tx][ty + i*8], h, l);
        th[(size_t)n * ldt + k0 + tx] = h;
        tl[(size_t)n * ldt + k0 + tx] = l;
    }
}

struct WsAll { const float* src[5]; bf16* th[5]; bf16* tl[5]; const float* aOb; };
__global__ void __launch_bounds__(256) wsplit_all(WsAll wa)
{
    if (blockIdx.z == 35) {
        if (blockIdx.x == 0 && blockIdx.y == 0 && threadIdx.x < DD)
            g_b56[threadIdx.x] = wa.aOb[5*DD + threadIdx.x] + wa.aOb[6*DD + threadIdx.x];
        return;
    }
    int fam = blockIdx.z / 7, mod = blockIdx.z % 7;
    wsplit_body(wa.src[fam] + (size_t)mod*DD*DD,
                wa.th[fam] + (size_t)mod*DD*DD, wa.tl[fam] + (size_t)mod*DD*DD,
                DD, DD);
}
__global__ void __launch_bounds__(256) wsplit_big(
    const float* __restrict__ W, bf16* __restrict__ Th, bf16* __restrict__ Tl,
    int K, int N, long long wstride, long long tstride)
{
    wsplit_body(W + (size_t)blockIdx.z * wstride,
                Th + (size_t)blockIdx.z * tstride, Tl + (size_t)blockIdx.z * tstride,
                N, K);
}

// ---------------- warp-per-row LayerNorm (batched over z) -------------------
struct LnS { const float* x; const float* g; const float* b; bf16* oh; bf16* ol; };
struct LnBatch { LnS s[3]; };

__global__ void __launch_bounds__(256) ln_kernel(LnBatch lb)
{
    LnS sl = lb.s[blockIdx.y];
    int wid = threadIdx.x >> 5, lane = threadIdx.x & 31;
    int row = blockIdx.x * 8 + wid;
    size_t base = (size_t)row * DD + lane * 8;

    float v[8];
    float4 p0 = *(const float4*)&sl.x[base];
    float4 p1 = *(const float4*)&sl.x[base + 4];
    v[0]=p0.x; v[1]=p0.y; v[2]=p0.z; v[3]=p0.w;
    v[4]=p1.x; v[5]=p1.y; v[6]=p1.z; v[7]=p1.w;

    float s = 0.f;
    #pragma unroll
    for (int i = 0; i < 8; i++) s += v[i];
    float mean = warp_sum(s) * (1.0f/DD);
    float q = 0.f;
    #pragma unroll
    for (int i = 0; i < 8; i++) { float d = v[i]-mean; q += d*d; }
    float rstd = rsqrtf(warp_sum(q) * (1.0f/DD) + 1e-5f);

    int c = lane * 8;
    float4 g0 = *(const float4*)&sl.g[c], g1 = *(const float4*)&sl.g[c+4];
    float4 b0 = *(const float4*)&sl.b[c], b1 = *(const float4*)&sl.b[c+4];
    float gg[8] = {g0.x,g0.y,g0.z,g0.w,g1.x,g1.y,g1.z,g1.w};
    float bb[8] = {b0.x,b0.y,b0.z,b0.w,b1.x,b1.y,b1.z,b1.w};
    float out[8];
    #pragma unroll
    for (int i = 0; i < 8; i++) out[i] = (v[i]-mean)*rstd*gg[i] + bb[i];
    store8(sl.oh, sl.ol, base, out);
}

// ---------------- fused split-K reduce + LN(s), warp-per-row ----------------
struct FRdS {
    const float* p; const float* bias; const float* res; float* dst; int nsplit;
    int nln;
    const float *lg0, *lb0; bf16 *oh0, *ol0;
    const float *lg1, *lb1; bf16 *oh1, *ol1;
};
struct FRdBatch { FRdS s[3]; };

__global__ void __launch_bounds__(256) fused_reduce_ln(FRdBatch rb)
{
    FRdS sl = rb.s[blockIdx.y];
    int wid = threadIdx.x >> 5, lane = threadIdx.x & 31;
    int row = blockIdx.x * 8 + wid;
    size_t base = (size_t)row * DD + lane * 8;
    int c = lane * 8;

    float a[8];
    {
        float4 p0 = *(const float4*)&sl.p[base];
        float4 p1 = *(const float4*)&sl.p[base + 4];
        a[0]=p0.x; a[1]=p0.y; a[2]=p0.z; a[3]=p0.w;
        a[4]=p1.x; a[5]=p1.y; a[6]=p1.z; a[7]=p1.w;
    }
    for (int s = 1; s < sl.nsplit; s++) {
        float4 p0 = *(const float4*)&sl.p[(size_t)s*MD + base];
        float4 p1 = *(const float4*)&sl.p[(size_t)s*MD + base + 4];
        a[0]+=p0.x; a[1]+=p0.y; a[2]+=p0.z; a[3]+=p0.w;
        a[4]+=p1.x; a[5]+=p1.y; a[6]+=p1.z; a[7]+=p1.w;
    }
    {
        float4 b0 = *(const float4*)&sl.bias[c], b1 = *(const float4*)&sl.bias[c+4];
        a[0]+=b0.x; a[1]+=b0.y; a[2]+=b0.z; a[3]+=b0.w;
        a[4]+=b1.x; a[5]+=b1.y; a[6]+=b1.z; a[7]+=b1.w;
    }
    if (sl.res) {
        float4 r0 = *(const float4*)&sl.res[base], r1 = *(const float4*)&sl.res[base+4];
        a[0]+=r0.x; a[1]+=r0.y; a[2]+=r0.z; a[3]+=r0.w;
        a[4]+=r1.x; a[5]+=r1.y; a[6]+=r1.z; a[7]+=r1.w;
    }
    {
        float4 o0 = make_float4(a[0],a[1],a[2],a[3]);
        float4 o1 = make_float4(a[4],a[5],a[6],a[7]);
        *(float4*)&sl.dst[base] = o0;
        *(float4*)&sl.dst[base+4] = o1;
    }

    float s = 0.f;
    #pragma unroll
    for (int i = 0; i < 8; i++) s += a[i];
    float mean = warp_sum(s) * (1.0f/DD);
    float q = 0.f;
    #pragma unroll
    for (int i = 0; i < 8; i++) { float d = a[i]-mean; q += d*d; }
    float rstd = rsqrtf(warp_sum(q) * (1.0f/DD) + 1e-5f);

    float nrm[8];
    #pragma unroll
    for (int i = 0; i < 8; i++) nrm[i] = (a[i]-mean)*rstd;

    {
        float4 g0 = *(const float4*)&sl.lg0[c], g1 = *(const float4*)&sl.lg0[c+4];
        float4 b0 = *(const float4*)&sl.lb0[c], b1 = *(const float4*)&sl.lb0[c+4];
        float gg[8] = {g0.x,g0.y,g0.z,g0.w,g1.x,g1.y,g1.z,g1.w};
        float bb[8] = {b0.x,b0.y,b0.z,b0.w,b1.x,b1.y,b1.z,b1.w};
        float out[8];
        #pragma unroll
        for (int i = 0; i < 8; i++) out[i] = nrm[i]*gg[i] + bb[i];
        store8(sl.oh0, sl.ol0, base, out);
    }
    if (sl.nln > 1) {
        float4 g0 = *(const float4*)&sl.lg1[c], g1 = *(const float4*)&sl.lg1[c+4];
        float4 b0 = *(const float4*)&sl.lb1[c], b1 = *(const float4*)&sl.lb1[c+4];
        float gg[8] = {g0.x,g0.y,g0.z,g0.w,g1.x,g1.y,g1.z,g1.w};
        float bb[8] = {b0.x,b0.y,b0.z,b0.w,b1.x,b1.y,b1.z,b1.w};
        float out[8];
        #pragma unroll
        for (int i = 0; i < 8; i++) out[i] = nrm[i]*gg[i] + bb[i];
        store8(sl.oh1, sl.ol1, base, out);
    }
}

// ---------------- batched split-compensated MMA GEMM ------------------------
struct Slice {
    const bf16 *Ah, *Al, *Bh, *Bl;
    const float *bias, *res;
    float* C; bf16 *Ch, *Cl;
    int mode, lda, ldb, Ksub;
};
struct Batch { Slice s[12]; };

#define BKC 32
#define LDSB 40
#define ARRE (128*LDSB)
#define STGE (4*ARRE)
#define GSMEM (2*STGE*2)

__device__ __forceinline__ void mma16816(float* c, const uint32_t* a, const uint32_t* b){
    asm volatile("mma.sync.aligned.m16n8k16.row.col.f32.bf16.bf16.f32 "
        "{%0,%1,%2,%3}, {%4,%5,%6,%7}, {%8,%9}, {%0,%1,%2,%3};"
        : "+f"(c[0]), "+f"(c[1]), "+f"(c[2]), "+f"(c[3])
        : "r"(a[0]), "r"(a[1]), "r"(a[2]), "r"(a[3]), "r"(b[0]), "r"(b[1]));
}

__global__ void __launch_bounds__(256,2)
gemm_batched(Batch bt, int M, int N)
{
    extern __shared__ __align__(16) bf16 smem[];
    const Slice sl = bt.s[blockIdx.z];
    const int tid  = threadIdx.x;
    const int warp = tid >> 5, lane = tid & 31;
    const int wm = warp >> 2, wn = warp & 3;
    const int row0 = blockIdx.y * 128, col0 = blockIdx.x * 128;
    const int g8 = lane >> 2, tig = lane & 3;
    const uint32_t sb = smem_u32(smem);
    const int NC = sl.Ksub / BKC;
    const int lda = sl.lda, ldb = sl.ldb;

    float acc[4][4][4];
    #pragma unroll
    for (int i=0;i<4;i++) for (int j=0;j<4;j++) for (int q=0;q<4;q++) acc[i][j][q]=0.f;

    const int ck0 = tid, ck1 = tid + 256;
    const int r0c = ck0 >> 2, c0c = (ck0 & 3) * 8;
    const int r1c = ck1 >> 2, c1c = (ck1 & 3) * 8;

    const int lmat = lane >> 3, lrow = lane & 7;
    const uint32_t a_lane_off = (uint32_t)(((lmat & 1) * 8 + lrow) * LDSB + (lmat >> 1) * 8) * 2;
    const uint32_t b_lane_off = (uint32_t)(((lmat >> 1) * 8 + lrow) * LDSB + (lmat & 1) * 8) * 2;

    auto cpStage = [&](int c, int st){
        int kc = c * BKC;
        uint32_t base = sb + (uint32_t)(st * STGE) * 2;
        uint32_t so0 = (uint32_t)(r0c * LDSB + c0c) * 2;
        uint32_t so1 = (uint32_t)(r1c * LDSB + c1c) * 2;
        cp16(base + so0,            sl.Ah + (size_t)(row0 + r0c) * lda + kc + c0c);
        cp16(base + so1,            sl.Ah + (size_t)(row0 + r1c) * lda + kc + c1c);
        cp16(base + ARRE*2 + so0,   sl.Al + (size_t)(row0 + r0c) * lda + kc + c0c);
        cp16(base + ARRE*2 + so1,   sl.Al + (size_t)(row0 + r1c) * lda + kc + c1c);
        cp16(base + ARRE*4 + so0,   sl.Bh + (size_t)(col0 + r0c) * ldb + kc + c0c);
        cp16(base + ARRE*4 + so1,   sl.Bh + (size_t)(col0 + r1c) * ldb + kc + c1c);
        cp16(base + ARRE*6 + so0,   sl.Bl + (size_t)(col0 + r0c) * ldb + kc + c0c);
        cp16(base + ARRE*6 + so1,   sl.Bl + (size_t)(col0 + r1c) * ldb + kc + c1c);
        asm volatile("cp.async.commit_group;" ::: "memory");
    };

    cpStage(0, 0);
    if (NC > 1) cpStage(1, 1);
    else asm volatile("cp.async.commit_group;" ::: "memory");

    for (int c = 0; c < NC; c++) {
        const int st = c & 1;
        if (c + 2 < NC) asm volatile("cp.async.wait_group 1;" ::: "memory");
        else            asm volatile("cp.async.wait_group 0;" ::: "memory");
        __syncthreads();

        const uint32_t sA_h = sb + (uint32_t)(st*STGE) * 2;
        const uint32_t sA_l = sA_h + ARRE*2;
        const uint32_t sB_h = sA_h + ARRE*4;
        const uint32_t sB_l = sA_h + ARRE*6;

        #pragma unroll
        for (int kk = 0; kk < 2; kk++) {
            const uint32_t kbo = (uint32_t)(kk * 16) * 2;
            uint32_t bh[4][2], bl[4][2];
            #pragma unroll
            for (int pr = 0; pr < 2; pr++) {
                uint32_t nbase = (uint32_t)((wn*32 + pr*16) * LDSB) * 2;
                uint32_t r4[4];
                ldsm_x4(r4, sB_h + nbase + kbo + b_lane_off);
                bh[pr*2][0] = r4[0]; bh[pr*2][1] = r4[1];
                bh[pr*2+1][0] = r4[2]; bh[pr*2+1][1] = r4[3];
                ldsm_x4(r4, sB_l + nbase + kbo + b_lane_off);
                bl[pr*2][0] = r4[0]; bl[pr*2][1] = r4[1];
                bl[pr*2+1][0] = r4[2]; bl[pr*2+1][1] = r4[3];
            }
            #pragma unroll
            for (int mi = 0; mi < 4; mi++) {
                uint32_t rbase = (uint32_t)((wm*64 + mi*16) * LDSB) * 2;
                uint32_t ah[4], al[4];
                ldsm_x4(ah, sA_h + rbase + kbo + a_lane_off);
                ldsm_x4(al, sA_l + rbase + kbo + a_lane_off);
                #pragma unroll
                for (int ni = 0; ni < 4; ni++) {
                    mma16816(acc[mi][ni], ah, bh[ni]);
                    mma16816(acc[mi][ni], ah, bl[ni]);
                    mma16816(acc[mi][ni], al, bh[ni]);
                }
            }
        }
        __syncthreads();
        if (c + 2 < NC) cpStage(c + 2, st);
    }

    #pragma unroll
    for (int mi = 0; mi < 4; mi++) {
        #pragma unroll
        for (int ni = 0; ni < 4; ni++) {
            int r1 = row0 + wm*64 + mi*16 + g8;
            int c1 = col0 + wn*32 + ni*8 + tig*2;
            #pragma unroll
            for (int q = 0; q < 4; q++) {
                int r = (q < 2) ? r1 : r1 + 8;
                int cc = c1 + (q & 1);
                float v = acc[mi][ni][q];
                if (sl.bias) v += sl.bias[cc];
                if (sl.mode == 1)      v = fmaxf(v, 0.f);
                else if (sl.mode == 2) v = 1.f / (1.f + __expf(-v));
                if (sl.Ch) {
                    bf16 h, l; split2(v, h, l);
                    sl.Ch[(size_t)r * N + cc] = h;
                    sl.Cl[(size_t)r * N + cc] = l;
                } else {
                    if (sl.res) v += sl.res[(size_t)r * N + cc];
                    sl.C[(size_t)r * N + cc] = v;
                }
            }
        }
    }
}

// ---------------- windowed attention core (batched over z) ------------------
struct AtS { const float* Q; const float* K; const float* V; const float* G;
             bf16* cth; bf16* ctl; };
struct AtBatch { AtS s[3]; };

__global__ void __launch_bounds__(256)
attn_core_kernel(AtBatch ab, const unsigned char* __restrict__ mask)
{
    AtS sl = ab.s[blockIdx.y];
    int idx  = blockIdx.x * blockDim.x + threadIdx.x;
    int gw   = idx >> 5;
    int lane = idx & 31;
    int s = gw & (SS - 1);
    int h = (gw >> 10) & (HH - 1);
    int n = gw >> 12;

    int base_q = (n * SS + s) * DD + h * CC;
    float q0 = sl.Q[base_q + lane];
    float q1 = sl.Q[base_q + 32 + lane];

    int t0 = s - WINSZ; if (t0 < 0) t0 = 0;
    int t1 = s + WINSZ; if (t1 > SS - 1) t1 = SS - 1;
    int cnt = t1 - t0 + 1;

    float sc[2 * WINSZ + 1];
    float mx = -1e30f;
    for (int i = 0; i < cnt; i++) {
        int t = t0 + i;
        float v;
        if (mask[n * SS + t]) v = -1e30f;
        else {
            int bk = (n * SS + t) * DD + h * CC;
            float p = q0 * sl.K[bk + lane] + q1 * sl.K[bk + 32 + lane];
            #pragma unroll
            for (int o = 16; o > 0; o >>= 1) p += __shfl_xor_sync(0xffffffffu, p, o);
            v = p * 0.125f;
        }
        sc[i] = v;
        mx = fmaxf(mx, v);
    }
    float denom = 0.f;
    for (int i = 0; i < cnt; i++) {
        float e = (sc[i] <= -1e29f) ? 0.f : __expf(sc[i] - mx);
        sc[i] = e; denom += e;
    }
    float inv = (denom > 0.f) ? (1.f / denom) : 0.f;
    float o0 = 0.f, o1 = 0.f;
    for (int i = 0; i < cnt; i++) {
        int bv = (n * SS + (t0 + i)) * DD + h * CC;
        float a = sc[i] * inv;
        o0 = fmaf(a, sl.V[bv + lane], o0);
        o1 = fmaf(a, sl.V[bv + 32 + lane], o1);
    }
    float v0 = o0 * sl.G[base_q + lane];
    float v1 = o1 * sl.G[base_q + 32 + lane];
    bf16 h0, l0, h1, l1;
    split2(v0, h0, l0); split2(v1, h1, l1);
    sl.cth[base_q + lane]      = h0;  sl.ctl[base_q + lane]      = l0;
    sl.cth[base_q + 32 + lane] = h1;  sl.ctl[base_q + 32 + lane] = l1;
}

// ---------------- host orchestration ----------------------------------------
extern "C" void kernel_launch(void* const* d_in, const int* in_sizes, int n_in,
                              void* d_out, int out_size)
{
    (void)in_sizes; (void)n_in; (void)out_size;
    const float* inL = (const float*)d_in[0];
    const float* inN = (const float*)d_in[1];
    const float* inO = (const float*)d_in[2];
    const unsigned char* mask = (const unsigned char*)d_in[3];
    const float* aWq = (const float*)d_in[4];
    const float* aWk = (const float*)d_in[5];
    const float* aWv = (const float*)d_in[6];
    const float* aGw = (const float*)d_in[7];
    const float* aGb = (const float*)d_in[8];
    const float* aOw = (const float*)d_in[9];
    const float* aOb = (const float*)d_in[10];
    const float* ln_g = (const float*)d_in[11];
    const float* ln_b = (const float*)d_in[12];
    const float* ff_g = (const float*)d_in[13];
    const float* ff_b = (const float*)d_in[14];
    const float* ff_w1 = (const float*)d_in[15];
    const float* ff_b1 = (const float*)d_in[16];
    const float* ff_w2 = (const float*)d_in[17];
    const float* ff_b2 = (const float*)d_in[18];

    float* L  = (float*)d_out;
    float* Nb = L + BSD;
    float* O  = Nb + BSD;
    float* X[3] = { L, Nb, O };

    cudaMemcpyAsync(L,  inL, (size_t)BSD * sizeof(float), cudaMemcpyDeviceToDevice);
    cudaMemcpyAsync(Nb, inN, (size_t)BSD * sizeof(float), cudaMemcpyDeviceToDevice);
    cudaMemcpyAsync(O,  inO, (size_t)BSD * sizeof(float), cudaMemcpyDeviceToDevice);

    void* pa;
    #define SYM(var, sym) cudaGetSymbolAddress(&pa, sym); auto var = (decltype(&sym[0]))pa;
    SYM(Qb, g_Q) SYM(Kb, g_Kb) SYM(Vb, g_Vb) SYM(Gg, g_Gb)
    SYM(lnh, g_lnh) SYM(lnl, g_lnl)
    SYM(cth, g_cth) SYM(ctl, g_ctl)
    SYM(hidh, g_hidh) SYM(hidl, g_hidl)
    SYM(b56, g_b56) SYM(part, g_part)
    SYM(wqh, g_WqTh) SYM(wql, g_WqTl) SYM(wkh, g_WkTh) SYM(wkl, g_WkTl)
    SYM(wvh, g_WvTh) SYM(wvl, g_WvTl) SYM(gwh, g_GwTh) SYM(gwl, g_GwTl)
    SYM(owh, g_OwTh) SYM(owl, g_OwTl)
    SYM(w1h, g_w1Th) SYM(w1l, g_w1Tl) SYM(w2h, g_w2Th) SYM(w2l, g_w2Tl)
    #undef SYM

    cudaFuncSetAttribute(gemm_batched, cudaFuncAttributeMaxDynamicSharedMemorySize, GSMEM);

    // ---- weight prep: 3 launches ----
    {
        WsAll wa;
        wa.src[0]=aWq; wa.src[1]=aWk; wa.src[2]=aWv; wa.src[3]=aGw; wa.src[4]=aOw;
        wa.th[0]=wqh; wa.th[1]=wkh; wa.th[2]=wvh; wa.th[3]=gwh; wa.th[4]=owh;
        wa.tl[0]=wql; wa.tl[1]=wkl; wa.tl[2]=wvl; wa.tl[3]=gwl; wa.tl[4]=owl;
        wa.aOb = aOb;
        wsplit_all<<<dim3(8, 8, 36), 256>>>(wa);
        wsplit_big<<<dim3(HID/32, DD/32, 6), 256>>>(ff_w1, w1h, w1l, DD, HID,
                                                    (long long)DD*HID, (long long)DD*HID);
        wsplit_big<<<dim3(DD/32, HID/32, 6), 256>>>(ff_w2, w2h, w2l, HID, DD,
                                                    (long long)HID*DD, (long long)HID*DD);
    }

    float* QKVG[4] = { Qb, Kb, Vb, Gg };
    auto LS = [&](int slot) { return lnh + (size_t)slot*BSD; };
    auto LSl = [&](int slot) { return lnl + (size_t)slot*BSD; };

    auto run_ln = [&](int nz, const float* xs[], const float* gbase, const float* bbase,
                      const int* ks, const int* slots) {
        LnBatch lb;
        for (int j = 0; j < nz; j++)
            lb.s[j] = { xs[j], gbase + (size_t)ks[j]*DD, bbase + (size_t)ks[j]*DD,
                        LS(slots[j]), LSl(slots[j]) };
        ln_kernel<<<dim3(MM/8, nz), 256>>>(lb);
    };

    auto run_qkvg = [&](int nz, const int* mods, const int* qslot, const int* kvslot) {
        Batch bt = {};
        for (int j = 0; j < nz; j++) {
            int k = mods[j];
            for (int c = 0; c < 4; c++) {
                Slice& s = bt.s[j*4 + c];
                int slot = (c == 0) ? qslot[j] : kvslot[j];
                s.Ah = LS(slot); s.Al = LSl(slot);
                const bf16* bh[4] = { wqh, wkh, wvh, gwh };
                const bf16* bl[4] = { wql, wkl, wvl, gwl };
                s.Bh = bh[c] + (size_t)k*DD*DD;
                s.Bl = bl[c] + (size_t)k*DD*DD;
                s.bias = (c == 3) ? (aGb + (size_t)k*DD) : nullptr;
                s.C = QKVG[c] + (size_t)j*BSD;
                s.mode = (c == 3) ? 2 : 0;
                s.lda = DD; s.ldb = DD; s.Ksub = DD;
            }
        }
        gemm_batched<<<dim3(DD/128, MM/128, nz*4), 256, GSMEM>>>(bt, MM, DD);
    };

    auto run_attn = [&](int nz) {
        AtBatch ab = {};
        for (int j = 0; j < nz; j++)
            ab.s[j] = { Qb + (size_t)j*BSD, Kb + (size_t)j*BSD, Vb + (size_t)j*BSD,
                        Gg + (size_t)j*BSD, cth + (size_t)j*BSD, ctl + (size_t)j*BSD };
        attn_core_kernel<<<dim3((BB*HH*SS*32)/256, nz), 256>>>(ab, mask);
    };

    // proj as split-K partials: slice j*2+sp -> part[(j*2+sp)*MD]
    auto run_proj_partials = [&](int nz, const int* mods) {
        Batch bt = {};
        for (int j = 0; j < nz; j++)
            for (int sp = 0; sp < 2; sp++) {
                Slice& s = bt.s[j*2 + sp];
                s.Ah = cth + (size_t)j*BSD + sp*128;
                s.Al = ctl + (size_t)j*BSD + sp*128;
                s.Bh = owh + (size_t)mods[j]*DD*DD + sp*128;
                s.Bl = owl + (size_t)mods[j]*DD*DD + sp*128;
                s.C = part + (size_t)(j*2 + sp)*MD;
                s.lda = DD; s.ldb = DD; s.Ksub = 128;
            }
        gemm_batched<<<dim3(DD/128, MM/128, nz*2), 256, GSMEM>>>(bt, MM, DD);
    };

    auto run_ff_gemms = [&](int nz, const int* mods, const int* lnslots) {
        Batch b1 = {};
        for (int j = 0; j < nz; j++) {
            Slice& s = b1.s[j];
            s.Ah = LS(lnslots[j]); s.Al = LSl(lnslots[j]);
            s.Bh = w1h + (size_t)mods[j]*DD*HID; s.Bl = w1l + (size_t)mods[j]*DD*HID;
            s.bias = ff_b1 + (size_t)mods[j]*HID;
            s.Ch = hidh + (size_t)j*MH; s.Cl = hidl + (size_t)j*MH;
            s.mode = 1; s.lda = DD; s.ldb = DD; s.Ksub = DD;
        }
        gemm_batched<<<dim3(HID/128, MM/128, nz), 256, GSMEM>>>(b1, MM, HID);
        Batch b2 = {};
        for (int j = 0; j < nz; j++)
            for (int sp = 0; sp < 4; sp++) {
                Slice& s = b2.s[j*4 + sp];
                s.Ah = hidh + (size_t)j*MH + sp*512;
                s.Al = hidl + (size_t)j*MH + sp*512;
                s.Bh = w2h + (size_t)mods[j]*HID*DD + sp*512;
                s.Bl = w2l + (size_t)mods[j]*HID*DD + sp*512;
                s.C = part + (size_t)(j*4 + sp)*MD;
                s.lda = HID; s.ldb = HID; s.Ksub = 512;
            }
        gemm_batched<<<dim3(DD/128, MM/128, nz*4), 256, GSMEM>>>(b2, MM, DD);
    };

    // initial block-LNs: ln0->4, ln1->5, ln2->6
    {
        const float* xs[3] = { L, Nb, O };
        const int lnk[3] = { 0, 1, 2 };
        const int slots[3] = { 4, 5, 6 };
        run_ln(3, xs, ln_g, ln_b, lnk, slots);
    }

    for (int it = 0; it < NITER; it++) {
        // -------- Phase 1: self blocks --------
        {
            const int mods[3] = { 0, 1, 2 };
            const int slots[3] = { 4, 5, 6 };
            run_qkvg(3, mods, slots, slots);
            run_attn(3);
            run_proj_partials(3, mods);
            // fused: X += proj + aOb  ;  FF-LN -> slots 0,1,2
            FRdBatch pr = {};
            for (int j = 0; j < 3; j++)
                pr.s[j] = { part + (size_t)j*2*MD, aOb + (size_t)mods[j]*DD, X[j], X[j], 2, 1,
                            ff_g + (size_t)mods[j]*DD, ff_b + (size_t)mods[j]*DD, LS(j), LSl(j),
                            nullptr, nullptr, nullptr, nullptr };
            fused_reduce_ln<<<dim3(MM/8, 3), 256>>>(pr);
            const int ffslots[3] = { 0, 1, 2 };
            run_ff_gemms(3, mods, ffslots);
            FRdBatch rb = {};
            rb.s[0] = { part + 0*4*MD, ff_b2 + 0*DD, L, L, 4, 1,
                        ln_g + 4*DD, ln_b + 4*DD, LS(0), LSl(0),
                        nullptr, nullptr, nullptr, nullptr };
            rb.s[1] = { part + 1*4*MD, ff_b2 + 1*DD, Nb, Nb, 4, 1,
                        ln_g + 5*DD, ln_b + 5*DD, LS(1), LSl(1),
                        nullptr, nullptr, nullptr, nullptr };
            rb.s[2] = { part + 2*4*MD, ff_b2 + 2*DD, O, O, 4, 2,
                        ln_g + 3*DD, ln_b + 3*DD, LS(3), LSl(3),
                        ln_g + 8*DD, ln_b + 8*DD, LS(2), LSl(2) };
            fused_reduce_ln<<<dim3(MM/8, 3), 256>>>(rb);
        }
        // -------- Phase 2: cross blocks --------
        {
            const int mods[2] = { 3, 4 };
            const int qslot[2] = { 0, 1 };
            const int kvslot[2] = { 3, 3 };
            run_qkvg(2, mods, qslot, kvslot);
            run_attn(2);
            run_proj_partials(2, mods);
            float* dst[2] = { L, Nb };
            FRdBatch pr = {};
            for (int j = 0; j < 2; j++)
                pr.s[j] = { part + (size_t)j*2*MD, aOb + (size_t)mods[j]*DD, dst[j], dst[j], 2, 1,
                            ff_g + (size_t)mods[j]*DD, ff_b + (size_t)mods[j]*DD, LS(j), LSl(j),
                            nullptr, nullptr, nullptr, nullptr };
            fused_reduce_ln<<<dim3(MM/8, 2), 256>>>(pr);
            const int ffslots[2] = { 0, 1 };
            run_ff_gemms(2, mods, ffslots);
            FRdBatch rb = {};
            rb.s[0] = { part + 0*4*MD, ff_b2 + 3*DD, L, L, 4, 2,
                        ln_g + 6*DD, ln_b + 6*DD, LS(0), LSl(0),
                        ln_g + 0*DD, ln_b + 0*DD, LS(4), LSl(4) };
            rb.s[1] = { part + 1*4*MD, ff_b2 + 4*DD, Nb, Nb, 4, 2,
                        ln_g + 7*DD, ln_b + 7*DD, LS(1), LSl(1),
                        ln_g + 1*DD, ln_b + 1*DD, LS(5), LSl(5) };
            fused_reduce_ln<<<dim3(MM/8, 2), 256>>>(rb);
        }
        // -------- Phase 3: O update --------
        {
            const int mods[2] = { 5, 6 };
            const int qslot[2] = { 2, 2 };
            const int kvslot[2] = { 1, 0 };
            run_qkvg(2, mods, qslot, kvslot);
            run_attn(2);
            // proj5 + proj6, each split-K x2: 4 partial slices
            Batch bp = {};
            for (int m = 0; m < 2; m++)
                for (int sp = 0; sp < 2; sp++) {
                    Slice& s = bp.s[m*2 + sp];
                    s.Ah = cth + (size_t)m*BSD + sp*128;
                    s.Al = ctl + (size_t)m*BSD + sp*128;
                    s.Bh = owh + (size_t)(5 + m)*DD*DD + sp*128;
                    s.Bl = owl + (size_t)(5 + m)*DD*DD + sp*128;
                    s.C = part + (size_t)(m*2 + sp)*MD;
                    s.lda = DD; s.ldb = DD; s.Ksub = 128;
                }
            gemm_batched<<<dim3(DD/128, MM/128, 4), 256, GSMEM>>>(bp, MM, DD);
            FRdBatch rp = {};
            rp.s[0] = { part, b56, O, O, 4, 1,
                        ff_g + 5*DD, ff_b + 5*DD, LS(0), LSl(0),
                        nullptr, nullptr, nullptr, nullptr };
            fused_reduce_ln<<<dim3(MM/8, 1), 256>>>(rp);
            const int ffm[1] = { 5 };
            const int ffslots[1] = { 0 };
            run_ff_gemms(1, ffm, ffslots);
            FRdBatch rb = {};
            rb.s[0] = { part, ff_b2 + 5*DD, O, O, 4, 1,
                        ln_g + 2*DD, ln_b + 2*DD, LS(6), LSl(6),
                        nullptr, nullptr, nullptr, nullptr };
            fused_reduce_ln<<<dim3(MM/8, 1), 256>>>(rb);
        }
    }
}